// round 1
// baseline (speedup 1.0000x reference)
#include <cuda_runtime.h>
#include <math.h>

// Problem constants
#define Bb  2
#define Ll  12
#define Nn  2048
#define Hh  64
#define NDe 32
#define TEe 10
#define Ff  148   // feat store: dy(64) + td(10) + dw(10) + embd(32) + embu(32)
#define F2  116   // WQ/WK input features: dy(64)+td(10)+dw(10)+emb(32)
#define KTt 3

static const size_t OUT_G = (size_t)Bb * Nn * KTt * Nn; // elements per output tensor g

// Scratch (allocation-free rule: device globals)
__device__ float g_feat[(size_t)Bb * Nn * Ff];       // ~4.9 MB
__device__ float g_Q[(size_t)4 * Nn * Hh];           // 2 MB  (combo c = v*2+b)
__device__ float g_K[(size_t)4 * Nn * Hh];           // 2 MB
__device__ float g_S[(size_t)4 * Nn * Nn];           // 64 MB raw scores
__device__ float g_A[(size_t)4 * Nn * Nn];           // 64 MB normalized adjacency

// ---------------------------------------------------------------------------
// Kernel 1: per-node feature prep: X@W1 -> relu -> BN -> @W2 -> dy_feat,
// then pack feat148 = [dy, T_D, D_W, embd, embu]
// ---------------------------------------------------------------------------
__global__ void __launch_bounds__(128) feat_kernel(
    const float* __restrict__ hist, const float* __restrict__ embd,
    const float* __restrict__ embu, const float* __restrict__ tdf,
    const float* __restrict__ dwf,
    const float* __restrict__ W1, const float* __restrict__ b1,
    const float* __restrict__ gamma, const float* __restrict__ beta,
    const float* __restrict__ mean, const float* __restrict__ var,
    const float* __restrict__ W2, const float* __restrict__ b2)
{
    int n = blockIdx.x, b = blockIdx.y, t = threadIdx.x;
    __shared__ float Xs[12];
    __shared__ float hs[128];
    __shared__ float fs[64];
    __shared__ float W1s[128 * 12];
    __shared__ float W2s[128 * 65];   // transposed [k][j], padded stride 65

    for (int i = t; i < 128 * 12; i += 128) W1s[i] = W1[i];
    for (int i = t; i < 64 * 128; i += 128) {
        int j = i >> 7, k = i & 127;
        W2s[k * 65 + j] = W2[i];
    }
    if (t < 12) Xs[t] = hist[(((size_t)b * Ll + t) * Nn + n) * 3];
    __syncthreads();

    {
        float acc = b1[t];
        #pragma unroll
        for (int l = 0; l < 12; l++) acc = fmaf(Xs[l], W1s[t * 12 + l], acc);
        acc = fmaxf(acc, 0.0f);
        acc = (acc - mean[t]) * (gamma[t] / sqrtf(var[t] + 1e-5f)) + beta[t];
        hs[t] = acc;
    }
    __syncthreads();

    if (t < 64) {
        float acc = b2[t];
        #pragma unroll 16
        for (int k = 0; k < 128; k++) acc = fmaf(hs[k], W2s[k * 65 + t], acc);
        fs[t] = acc;
    }
    __syncthreads();

    float* fr = g_feat + ((size_t)b * Nn + n) * Ff;
    size_t tbase = (((size_t)b * Ll + (Ll - 1)) * Nn + n) * TEe;
    for (int f = t; f < Ff; f += 128) {
        float val;
        if      (f < 64)  val = fs[f];
        else if (f < 74)  val = tdf[tbase + f - 64];
        else if (f < 84)  val = dwf[tbase + f - 74];
        else if (f < 116) val = embd[(size_t)n * NDe + (f - 84)];
        else              val = embu[(size_t)n * NDe + (f - 116)];
        fr[f] = val;
    }
}

// ---------------------------------------------------------------------------
// Kernel 2: Q/K projections for both variants.
// Block: 128 nodes; threads map to (variant, Q/K, j). Weights + feat staged in
// dynamic smem (transposed) for conflict-free reuse.
// ---------------------------------------------------------------------------
#define QK_SMEM ((Ff * 128 + 2 * F2 * 64) * (int)sizeof(float))  // 135168 B

__global__ void __launch_bounds__(256) qk_kernel(
    const float* __restrict__ WQ, const float* __restrict__ WK)
{
    extern __shared__ float sm[];
    float* Fs  = sm;                 // [f][node] : Ff x 128
    float* WQt = Fs + Ff * 128;      // [f][j]    : F2 x 64
    float* WKt = WQt + F2 * 64;

    int node0 = blockIdx.x * 128;
    int b = blockIdx.y;
    int t = threadIdx.x;

    for (int i = t; i < 128 * Ff; i += 256) {
        int node = i / Ff, f = i - node * Ff;
        Fs[f * 128 + node] = g_feat[((size_t)b * Nn + node0 + node) * Ff + f];
    }
    for (int i = t; i < 64 * F2; i += 256) {
        int j = i / F2, f = i - j * F2;
        WQt[f * 64 + j] = WQ[i];
        WKt[f * 64 + j] = WK[i];
    }
    __syncthreads();

    int v = t >> 7, sel = (t >> 6) & 1, j = t & 63;
    const float* Wt = sel ? WKt : WQt;
    float* dst = (sel ? g_K : g_Q) + (size_t)(v * 2 + b) * Nn * Hh;
    int ebase = 84 + 32 * v;  // which embedding slice in feat148

    for (int nb = 0; nb < 128; nb += 8) {
        float acc[8] = {0, 0, 0, 0, 0, 0, 0, 0};
        for (int f = 0; f < 84; f++) {
            float w = Wt[f * 64 + j];
            #pragma unroll
            for (int u = 0; u < 8; u++)
                acc[u] = fmaf(Fs[f * 128 + nb + u], w, acc[u]);
        }
        #pragma unroll 8
        for (int e = 0; e < 32; e++) {
            float w = Wt[(84 + e) * 64 + j];
            #pragma unroll
            for (int u = 0; u < 8; u++)
                acc[u] = fmaf(Fs[(ebase + e) * 128 + nb + u], w, acc[u]);
        }
        #pragma unroll
        for (int u = 0; u < 8; u++)
            dst[(size_t)(node0 + nb + u) * Hh + j] = acc[u];
    }
}

// ---------------------------------------------------------------------------
// Kernel 3: scores = Q @ K^T * 1/sqrt(H)   (4 combos, 2048x2048x64)
// 128x128 block tile, 8x8 per thread, K staged in two 32-wide smem tiles.
// ---------------------------------------------------------------------------
__global__ void __launch_bounds__(256) scores_kernel()
{
    int c = blockIdx.z;
    const float* Q = g_Q + (size_t)c * Nn * Hh;
    const float* K = g_K + (size_t)c * Nn * Hh;
    float* S = g_S + (size_t)c * Nn * Nn;
    int row0 = blockIdx.y * 128, col0 = blockIdx.x * 128;

    __shared__ float Qs[32][128];
    __shared__ float Ks[32][128];

    int t = threadIdx.x;
    int tx = t & 15, ty = t >> 4;
    float acc[8][8] = {};

    for (int k0 = 0; k0 < Hh; k0 += 32) {
        #pragma unroll
        for (int it = 0; it < 4; it++) {
            int idx = t + it * 256;      // 0..1023
            int r = idx >> 3;            // 0..127
            int kq = (idx & 7) * 4;      // 0..28
            float4 q4 = *(const float4*)(Q + (size_t)(row0 + r) * Hh + k0 + kq);
            Qs[kq + 0][r] = q4.x; Qs[kq + 1][r] = q4.y;
            Qs[kq + 2][r] = q4.z; Qs[kq + 3][r] = q4.w;
            float4 k4 = *(const float4*)(K + (size_t)(col0 + r) * Hh + k0 + kq);
            Ks[kq + 0][r] = k4.x; Ks[kq + 1][r] = k4.y;
            Ks[kq + 2][r] = k4.z; Ks[kq + 3][r] = k4.w;
        }
        __syncthreads();
        #pragma unroll
        for (int kk = 0; kk < 32; kk++) {
            float a[8], bb[8];
            *(float4*)&a[0]  = *(const float4*)&Qs[kk][ty * 8];
            *(float4*)&a[4]  = *(const float4*)&Qs[kk][ty * 8 + 4];
            *(float4*)&bb[0] = *(const float4*)&Ks[kk][tx * 8];
            *(float4*)&bb[4] = *(const float4*)&Ks[kk][tx * 8 + 4];
            #pragma unroll
            for (int i = 0; i < 8; i++)
                #pragma unroll
                for (int jj = 0; jj < 8; jj++)
                    acc[i][jj] = fmaf(a[i], bb[jj], acc[i][jj]);
        }
        __syncthreads();
    }

    #pragma unroll
    for (int i = 0; i < 8; i++) {
        int rr = row0 + ty * 8 + i;
        float4 o0 = make_float4(acc[i][0] * 0.125f, acc[i][1] * 0.125f,
                                acc[i][2] * 0.125f, acc[i][3] * 0.125f);
        float4 o1 = make_float4(acc[i][4] * 0.125f, acc[i][5] * 0.125f,
                                acc[i][6] * 0.125f, acc[i][7] * 0.125f);
        *(float4*)(S + (size_t)rr * Nn + col0 + tx * 8)     = o0;
        *(float4*)(S + (size_t)rr * Nn + col0 + tx * 8 + 4) = o1;
    }
}

// ---------------------------------------------------------------------------
// Kernel 4: fused masked softmax + row-normalize. Softmax denominator cancels
// against the renormalization: A[n,m] = (mask+1e-7)*exp(s-max) / sum.
// Also writes the order-1 output (A * offdiag, replicated KT=3 times).
// ---------------------------------------------------------------------------
__global__ void __launch_bounds__(256) softmax_kernel(
    const float* __restrict__ mask0, const float* __restrict__ mask1,
    float* __restrict__ out)
{
    int n = blockIdx.x, c = blockIdx.y, v = c >> 1, b = c & 1;
    int t = threadIdx.x;
    const float* srow = g_S + ((size_t)c * Nn + n) * Nn;
    const float* mrow = (v ? mask1 : mask0) + (size_t)n * Nn;

    float s[8];
    float lmax = -3.4e38f;
    #pragma unroll
    for (int i = 0; i < 8; i++) {
        s[i] = srow[t + i * 256];
        lmax = fmaxf(lmax, s[i]);
    }

    __shared__ float red[8];
    #pragma unroll
    for (int o = 16; o; o >>= 1)
        lmax = fmaxf(lmax, __shfl_xor_sync(0xffffffffu, lmax, o));
    if ((t & 31) == 0) red[t >> 5] = lmax;
    __syncthreads();
    float rmax = red[0];
    #pragma unroll
    for (int w = 1; w < 8; w++) rmax = fmaxf(rmax, red[w]);
    __syncthreads();

    float wv[8], lsum = 0.0f;
    #pragma unroll
    for (int i = 0; i < 8; i++) {
        wv[i] = (mrow[t + i * 256] + 1e-7f) * expf(s[i] - rmax);
        lsum += wv[i];
    }
    #pragma unroll
    for (int o = 16; o; o >>= 1)
        lsum += __shfl_xor_sync(0xffffffffu, lsum, o);
    if ((t & 31) == 0) red[t >> 5] = lsum;
    __syncthreads();
    float tot = 0.0f;
    #pragma unroll
    for (int w = 0; w < 8; w++) tot += red[w];
    float inv = 1.0f / tot;

    float* arow = g_A + ((size_t)c * Nn + n) * Nn;
    float* orow = out + (size_t)(v * 2) * OUT_G + (size_t)(b * Nn + n) * KTt * Nn;
    #pragma unroll
    for (int i = 0; i < 8; i++) {
        int m = t + i * 256;
        float val = wv[i] * inv;
        arow[m] = val;
        float ov = (m == n) ? 0.0f : val;
        orow[m] = ov;
        orow[Nn + m] = ov;
        orow[2 * Nn + m] = ov;
    }
}

// ---------------------------------------------------------------------------
// Kernel 5: C = A @ A (2048^3, 4 combos), epilogue writes order-2 output
// directly (offdiag-zeroed, replicated KT=3 times) — C never hits scratch.
// ---------------------------------------------------------------------------
__global__ void __launch_bounds__(256) sq_kernel(float* __restrict__ out)
{
    int c = blockIdx.z, v = c >> 1, b = c & 1;
    const float* A = g_A + (size_t)c * Nn * Nn;
    int row0 = blockIdx.y * 128, col0 = blockIdx.x * 128;

    __shared__ float As[16][128];
    __shared__ float Bs[16][128];

    int t = threadIdx.x;
    int tx = t & 15, ty = t >> 4;
    float acc[8][8] = {};

    for (int k0 = 0; k0 < Nn; k0 += 16) {
        #pragma unroll
        for (int it = 0; it < 2; it++) {
            int idx = t + it * 256;      // 0..511
            int r = idx >> 2;            // 0..127
            int kq = (idx & 3) * 4;      // 0,4,8,12
            float4 a4 = *(const float4*)(A + (size_t)(row0 + r) * Nn + k0 + kq);
            As[kq + 0][r] = a4.x; As[kq + 1][r] = a4.y;
            As[kq + 2][r] = a4.z; As[kq + 3][r] = a4.w;
            int kk = idx >> 5;           // 0..15
            int cq = (idx & 31) * 4;
            *(float4*)&Bs[kk][cq] =
                *(const float4*)(A + (size_t)(k0 + kk) * Nn + col0 + cq);
        }
        __syncthreads();
        #pragma unroll
        for (int kk = 0; kk < 16; kk++) {
            float a[8], bb[8];
            *(float4*)&a[0]  = *(const float4*)&As[kk][ty * 8];
            *(float4*)&a[4]  = *(const float4*)&As[kk][ty * 8 + 4];
            *(float4*)&bb[0] = *(const float4*)&Bs[kk][tx * 8];
            *(float4*)&bb[4] = *(const float4*)&Bs[kk][tx * 8 + 4];
            #pragma unroll
            for (int i = 0; i < 8; i++)
                #pragma unroll
                for (int jj = 0; jj < 8; jj++)
                    acc[i][jj] = fmaf(a[i], bb[jj], acc[i][jj]);
        }
        __syncthreads();
    }

    float* obase = out + (size_t)(v * 2 + 1) * OUT_G;
    #pragma unroll
    for (int i = 0; i < 8; i++) {
        int n = row0 + ty * 8 + i;
        float vals[8];
        #pragma unroll
        for (int jj = 0; jj < 8; jj++)
            vals[jj] = (n == col0 + tx * 8 + jj) ? 0.0f : acc[i][jj];
        size_t rb = (size_t)(b * Nn + n) * KTt * Nn + col0 + tx * 8;
        float4 o0 = *(float4*)&vals[0];
        float4 o1 = *(float4*)&vals[4];
        #pragma unroll
        for (int tt = 0; tt < KTt; tt++) {
            *(float4*)(obase + rb + (size_t)tt * Nn)     = o0;
            *(float4*)(obase + rb + (size_t)tt * Nn + 4) = o1;
        }
    }
}

// ---------------------------------------------------------------------------
extern "C" void kernel_launch(void* const* d_in, const int* in_sizes, int n_in,
                              void* d_out, int out_size)
{
    const float* hist = (const float*)d_in[0];
    const float* embd = (const float*)d_in[1];
    const float* embu = (const float*)d_in[2];
    const float* tdf  = (const float*)d_in[3];
    const float* dwf  = (const float*)d_in[4];
    const float* m0   = (const float*)d_in[5];
    const float* m1   = (const float*)d_in[6];
    const float* W1   = (const float*)d_in[7];
    const float* b1   = (const float*)d_in[8];
    const float* gam  = (const float*)d_in[9];
    const float* bet  = (const float*)d_in[10];
    const float* mu   = (const float*)d_in[11];
    const float* var  = (const float*)d_in[12];
    const float* W2   = (const float*)d_in[13];
    const float* b2   = (const float*)d_in[14];
    const float* WQ   = (const float*)d_in[15];
    const float* WK   = (const float*)d_in[16];
    float* out = (float*)d_out;

    cudaFuncSetAttribute(qk_kernel, cudaFuncAttributeMaxDynamicSharedMemorySize,
                         QK_SMEM);

    feat_kernel<<<dim3(Nn, Bb), 128>>>(hist, embd, embu, tdf, dwf,
                                       W1, b1, gam, bet, mu, var, W2, b2);
    qk_kernel<<<dim3(Nn / 128, Bb), 256, QK_SMEM>>>(WQ, WK);
    scores_kernel<<<dim3(16, 16, 4), 256>>>();
    softmax_kernel<<<dim3(Nn, 4), 256>>>(m0, m1, out);
    sq_kernel<<<dim3(16, 16, 4), 256>>>(out);
}

// round 3
// speedup vs baseline: 1.8107x; 1.8107x over previous
#include <cuda_runtime.h>
#include <cuda_bf16.h>
#include <math.h>
#include <cstdint>

// Problem constants
#define Bb  2
#define Ll  12
#define Nn  2048
#define Hh  64
#define NDe 32
#define TEe 10
#define Ff  148
#define F2  116
#define KTt 3

static const size_t OUT_G = (size_t)Bb * Nn * KTt * Nn;

// Scratch (allocation-free rule: device globals)
__device__ float g_feat[(size_t)Bb * Nn * Ff];
__device__ float g_Q[(size_t)4 * Nn * Hh];
__device__ float g_K[(size_t)4 * Nn * Hh];
__device__ float g_S[(size_t)4 * Nn * Nn];
__device__ __nv_bfloat16 g_Ah[(size_t)4 * Nn * Nn];  // A hi (bf16), row-major [m][k]
__device__ __nv_bfloat16 g_Al[(size_t)4 * Nn * Nn];  // A lo
__device__ __nv_bfloat16 g_Bh[(size_t)4 * Nn * Nn];  // A^T hi, [n][k]
__device__ __nv_bfloat16 g_Bl[(size_t)4 * Nn * Nn];  // A^T lo

// ===========================================================================
// Baseline-ISA helpers (no sm_103a-only instructions — ptxas targets sm_103)
// ===========================================================================
__device__ __forceinline__ void cpa16(uint32_t dst, const void* src) {
    asm volatile("cp.async.cg.shared.global [%0], [%1], 16;"
                 :: "r"(dst), "l"(src));
}
__device__ __forceinline__ void cpa_commit() {
    asm volatile("cp.async.commit_group;" ::: "memory");
}
template <int N> __device__ __forceinline__ void cpa_wait() {
    asm volatile("cp.async.wait_group %0;" :: "n"(N) : "memory");
}
__device__ __forceinline__ uint32_t s2u(const void* p) {
    uint32_t a;
    asm("{ .reg .u64 t; cvta.to.shared.u64 t, %1; cvt.u32.u64 %0, t; }"
        : "=r"(a) : "l"(p));
    return a;
}
__device__ __forceinline__ void mma16816(float* d, const uint32_t* a,
                                         const uint32_t* b) {
    asm volatile(
        "mma.sync.aligned.m16n8k16.row.col.f32.bf16.bf16.f32 "
        "{%0,%1,%2,%3}, {%4,%5,%6,%7}, {%8,%9}, {%0,%1,%2,%3};"
        : "+f"(d[0]), "+f"(d[1]), "+f"(d[2]), "+f"(d[3])
        : "r"(a[0]), "r"(a[1]), "r"(a[2]), "r"(a[3]), "r"(b[0]), "r"(b[1]));
}
__device__ __forceinline__ uint32_t ld32s(const __nv_bfloat16* p) {
    return *(const uint32_t*)p;
}

// ---------------------------------------------------------------------------
// Kernel 1: per-node feature prep (unchanged)
// ---------------------------------------------------------------------------
__global__ void __launch_bounds__(128) feat_kernel(
    const float* __restrict__ hist, const float* __restrict__ embd,
    const float* __restrict__ embu, const float* __restrict__ tdf,
    const float* __restrict__ dwf,
    const float* __restrict__ W1, const float* __restrict__ b1,
    const float* __restrict__ gamma, const float* __restrict__ beta,
    const float* __restrict__ mean, const float* __restrict__ var,
    const float* __restrict__ W2, const float* __restrict__ b2)
{
    int n = blockIdx.x, b = blockIdx.y, t = threadIdx.x;
    __shared__ float Xs[12];
    __shared__ float hs[128];
    __shared__ float fs[64];
    __shared__ float W1s[128 * 12];
    __shared__ float W2s[128 * 65];

    for (int i = t; i < 128 * 12; i += 128) W1s[i] = W1[i];
    for (int i = t; i < 64 * 128; i += 128) {
        int j = i >> 7, k = i & 127;
        W2s[k * 65 + j] = W2[i];
    }
    if (t < 12) Xs[t] = hist[(((size_t)b * Ll + t) * Nn + n) * 3];
    __syncthreads();

    {
        float acc = b1[t];
        #pragma unroll
        for (int l = 0; l < 12; l++) acc = fmaf(Xs[l], W1s[t * 12 + l], acc);
        acc = fmaxf(acc, 0.0f);
        acc = (acc - mean[t]) * (gamma[t] / sqrtf(var[t] + 1e-5f)) + beta[t];
        hs[t] = acc;
    }
    __syncthreads();

    if (t < 64) {
        float acc = b2[t];
        #pragma unroll 16
        for (int k = 0; k < 128; k++) acc = fmaf(hs[k], W2s[k * 65 + t], acc);
        fs[t] = acc;
    }
    __syncthreads();

    float* fr = g_feat + ((size_t)b * Nn + n) * Ff;
    size_t tbase = (((size_t)b * Ll + (Ll - 1)) * Nn + n) * TEe;
    for (int f = t; f < Ff; f += 128) {
        float val;
        if      (f < 64)  val = fs[f];
        else if (f < 74)  val = tdf[tbase + f - 64];
        else if (f < 84)  val = dwf[tbase + f - 74];
        else if (f < 116) val = embd[(size_t)n * NDe + (f - 84)];
        else              val = embu[(size_t)n * NDe + (f - 116)];
        fr[f] = val;
    }
}

// ---------------------------------------------------------------------------
// Kernel 2: Q/K projections (unchanged)
// ---------------------------------------------------------------------------
#define QK_SMEM ((Ff * 128 + 2 * F2 * 64) * (int)sizeof(float))

__global__ void __launch_bounds__(256) qk_kernel(
    const float* __restrict__ WQ, const float* __restrict__ WK)
{
    extern __shared__ float sm[];
    float* Fs  = sm;
    float* WQt = Fs + Ff * 128;
    float* WKt = WQt + F2 * 64;

    int node0 = blockIdx.x * 128;
    int b = blockIdx.y;
    int t = threadIdx.x;

    for (int i = t; i < 128 * Ff; i += 256) {
        int node = i / Ff, f = i - node * Ff;
        Fs[f * 128 + node] = g_feat[((size_t)b * Nn + node0 + node) * Ff + f];
    }
    for (int i = t; i < 64 * F2; i += 256) {
        int j = i / F2, f = i - j * F2;
        WQt[f * 64 + j] = WQ[i];
        WKt[f * 64 + j] = WK[i];
    }
    __syncthreads();

    int v = t >> 7, sel = (t >> 6) & 1, j = t & 63;
    const float* Wt = sel ? WKt : WQt;
    float* dst = (sel ? g_K : g_Q) + (size_t)(v * 2 + b) * Nn * Hh;
    int ebase = 84 + 32 * v;

    for (int nb = 0; nb < 128; nb += 8) {
        float acc[8] = {0, 0, 0, 0, 0, 0, 0, 0};
        for (int f = 0; f < 84; f++) {
            float w = Wt[f * 64 + j];
            #pragma unroll
            for (int u = 0; u < 8; u++)
                acc[u] = fmaf(Fs[f * 128 + nb + u], w, acc[u]);
        }
        #pragma unroll 8
        for (int e = 0; e < 32; e++) {
            float w = Wt[(84 + e) * 64 + j];
            #pragma unroll
            for (int u = 0; u < 8; u++)
                acc[u] = fmaf(Fs[(ebase + e) * 128 + nb + u], w, acc[u]);
        }
        #pragma unroll
        for (int u = 0; u < 8; u++)
            dst[(size_t)(node0 + nb + u) * Hh + j] = acc[u];
    }
}

// ---------------------------------------------------------------------------
// Kernel 3: scores = Q @ K^T * 1/sqrt(H) (unchanged)
// ---------------------------------------------------------------------------
__global__ void __launch_bounds__(256) scores_kernel()
{
    int c = blockIdx.z;
    const float* Q = g_Q + (size_t)c * Nn * Hh;
    const float* K = g_K + (size_t)c * Nn * Hh;
    float* S = g_S + (size_t)c * Nn * Nn;
    int row0 = blockIdx.y * 128, col0 = blockIdx.x * 128;

    __shared__ float Qs[32][128];
    __shared__ float Ks[32][128];

    int t = threadIdx.x;
    int tx = t & 15, ty = t >> 4;
    float acc[8][8] = {};

    for (int k0 = 0; k0 < Hh; k0 += 32) {
        #pragma unroll
        for (int it = 0; it < 4; it++) {
            int idx = t + it * 256;
            int r = idx >> 3;
            int kq = (idx & 7) * 4;
            float4 q4 = *(const float4*)(Q + (size_t)(row0 + r) * Hh + k0 + kq);
            Qs[kq + 0][r] = q4.x; Qs[kq + 1][r] = q4.y;
            Qs[kq + 2][r] = q4.z; Qs[kq + 3][r] = q4.w;
            float4 k4 = *(const float4*)(K + (size_t)(col0 + r) * Hh + k0 + kq);
            Ks[kq + 0][r] = k4.x; Ks[kq + 1][r] = k4.y;
            Ks[kq + 2][r] = k4.z; Ks[kq + 3][r] = k4.w;
        }
        __syncthreads();
        #pragma unroll
        for (int kk = 0; kk < 32; kk++) {
            float a[8], bb[8];
            *(float4*)&a[0]  = *(const float4*)&Qs[kk][ty * 8];
            *(float4*)&a[4]  = *(const float4*)&Qs[kk][ty * 8 + 4];
            *(float4*)&bb[0] = *(const float4*)&Ks[kk][tx * 8];
            *(float4*)&bb[4] = *(const float4*)&Ks[kk][tx * 8 + 4];
            #pragma unroll
            for (int i = 0; i < 8; i++)
                #pragma unroll
                for (int jj = 0; jj < 8; jj++)
                    acc[i][jj] = fmaf(a[i], bb[jj], acc[i][jj]);
        }
        __syncthreads();
    }

    #pragma unroll
    for (int i = 0; i < 8; i++) {
        int rr = row0 + ty * 8 + i;
        float4 o0 = make_float4(acc[i][0] * 0.125f, acc[i][1] * 0.125f,
                                acc[i][2] * 0.125f, acc[i][3] * 0.125f);
        float4 o1 = make_float4(acc[i][4] * 0.125f, acc[i][5] * 0.125f,
                                acc[i][6] * 0.125f, acc[i][7] * 0.125f);
        *(float4*)(S + (size_t)rr * Nn + col0 + tx * 8)     = o0;
        *(float4*)(S + (size_t)rr * Nn + col0 + tx * 8 + 4) = o1;
    }
}

// ---------------------------------------------------------------------------
// Kernel 4: fused masked softmax + normalize; emits order-1 output + hi/lo A
// ---------------------------------------------------------------------------
__global__ void __launch_bounds__(256) softmax_kernel(
    const float* __restrict__ mask0, const float* __restrict__ mask1,
    float* __restrict__ out)
{
    int n = blockIdx.x, c = blockIdx.y, v = c >> 1, b = c & 1;
    int t = threadIdx.x;
    const float* srow = g_S + ((size_t)c * Nn + n) * Nn;
    const float* mrow = (v ? mask1 : mask0) + (size_t)n * Nn;

    float s[8];
    float lmax = -3.4e38f;
    #pragma unroll
    for (int i = 0; i < 8; i++) {
        s[i] = srow[t + i * 256];
        lmax = fmaxf(lmax, s[i]);
    }

    __shared__ float red[8];
    #pragma unroll
    for (int o = 16; o; o >>= 1)
        lmax = fmaxf(lmax, __shfl_xor_sync(0xffffffffu, lmax, o));
    if ((t & 31) == 0) red[t >> 5] = lmax;
    __syncthreads();
    float rmax = red[0];
    #pragma unroll
    for (int w = 1; w < 8; w++) rmax = fmaxf(rmax, red[w]);
    __syncthreads();

    float wv[8], lsum = 0.0f;
    #pragma unroll
    for (int i = 0; i < 8; i++) {
        wv[i] = (mrow[t + i * 256] + 1e-7f) * expf(s[i] - rmax);
        lsum += wv[i];
    }
    #pragma unroll
    for (int o = 16; o; o >>= 1)
        lsum += __shfl_xor_sync(0xffffffffu, lsum, o);
    if ((t & 31) == 0) red[t >> 5] = lsum;
    __syncthreads();
    float tot = 0.0f;
    #pragma unroll
    for (int w = 0; w < 8; w++) tot += red[w];
    float inv = 1.0f / tot;

    size_t abase = ((size_t)c * Nn + n) * Nn;
    float* orow = out + (size_t)(v * 2) * OUT_G + (size_t)(b * Nn + n) * KTt * Nn;
    #pragma unroll
    for (int i = 0; i < 8; i++) {
        int m = t + i * 256;
        float val = wv[i] * inv;
        __nv_bfloat16 h = __float2bfloat16(val);
        float lo = val - __bfloat162float(h);
        g_Ah[abase + m] = h;
        g_Al[abase + m] = __float2bfloat16(lo);
        float ov = (m == n) ? 0.0f : val;
        orow[m] = ov;
        orow[Nn + m] = ov;
        orow[2 * Nn + m] = ov;
    }
}

// ---------------------------------------------------------------------------
// Kernel 4b: transpose hi/lo A -> B operand (B[n][k] = A[k][n])
// ---------------------------------------------------------------------------
__global__ void __launch_bounds__(256) transpose_kernel()
{
    __shared__ __nv_bfloat16 th[64][65];
    __shared__ __nv_bfloat16 tl[64][65];
    int c = blockIdx.z;
    size_t cb = (size_t)c * Nn * Nn;
    int r0 = blockIdx.y * 64, c0 = blockIdx.x * 64;
    int t = threadIdx.x;
    for (int i = t; i < 64 * 64; i += 256) {
        int r = i >> 6, cc = i & 63;
        size_t src = cb + (size_t)(r0 + r) * Nn + c0 + cc;
        th[r][cc] = g_Ah[src];
        tl[r][cc] = g_Al[src];
    }
    __syncthreads();
    for (int i = t; i < 64 * 64; i += 256) {
        int r = i >> 6, cc = i & 63;
        size_t dst = cb + (size_t)(c0 + r) * Nn + r0 + cc;
        g_Bh[dst] = th[cc][r];
        g_Bl[dst] = tl[cc][r];
    }
}

// ---------------------------------------------------------------------------
// Kernel 5: C = A @ A via mma.sync bf16 hi/lo (3 products into one acc).
// CTA 128x128, 8 warps (2x4) of 64x32, K-chunk 32, double-buffered cp.async.
// Epilogue writes order-2 output directly (diag zero, KT=3 replication).
// ---------------------------------------------------------------------------
#define SQSTRIDE 40                        // bf16 elems per smem row (32+8 pad)
#define ARR_B (128 * SQSTRIDE * 2)         // 10240 B per array
#define BUF_B (4 * ARR_B)                  // Ah,Al,Bh,Bl
#define SQ_SMEM (2 * BUF_B)                // 81920 B

__global__ void __launch_bounds__(256, 1) sq_mma_kernel(float* __restrict__ out)
{
    extern __shared__ char dsm[];
    int c = blockIdx.z, v = c >> 1, b = c & 1;
    int row0 = blockIdx.y * 128, col0 = blockIdx.x * 128;
    int t = threadIdx.x, wid = t >> 5, lane = t & 31;
    int g = lane >> 2, tig = lane & 3;
    int wm = wid >> 2, wn = wid & 3;           // warp tile: 64x32

    size_t cb = (size_t)c * Nn * Nn;
    const __nv_bfloat16* Ahg = g_Ah + cb;
    const __nv_bfloat16* Alg = g_Al + cb;
    const __nv_bfloat16* Bhg = g_Bh + cb;
    const __nv_bfloat16* Blg = g_Bl + cb;

    uint32_t sbase = s2u(dsm);
    float acc[4][4][4] = {};

    auto load_stage = [&](int s, int kc) {
        uint32_t sb = sbase + (uint32_t)s * BUF_B;
        int k0 = kc * 32;
        int r = ((0) << 6) + (t >> 2);   // reused below
        int seg = t & 3;
        #pragma unroll
        for (int j = 0; j < 8; j++) {
            int arr = j >> 1;
            int rr = ((j & 1) << 6) + (t >> 2);    // 0..127
            const __nv_bfloat16* base =
                (arr == 0) ? Ahg : (arr == 1) ? Alg : (arr == 2) ? Bhg : Blg;
            int grow = ((arr < 2) ? row0 : col0) + rr;
            cpa16(sb + (uint32_t)arr * ARR_B + rr * (SQSTRIDE * 2) + seg * 16,
                  base + (size_t)grow * Nn + k0 + seg * 8);
        }
        (void)r;
        cpa_commit();
    };

    load_stage(0, 0);

    int buf = 0;
    for (int kc = 0; kc < 64; kc++) {
        if (kc + 1 < 64) {
            load_stage(buf ^ 1, kc + 1);
            cpa_wait<1>();
        } else {
            cpa_wait<0>();
        }
        __syncthreads();

        const __nv_bfloat16* As  = (const __nv_bfloat16*)(dsm + buf * BUF_B);
        const __nv_bfloat16* Als = As  + 128 * SQSTRIDE;
        const __nv_bfloat16* Bs  = Als + 128 * SQSTRIDE;
        const __nv_bfloat16* Bls = Bs  + 128 * SQSTRIDE;

        #pragma unroll
        for (int ks = 0; ks < 2; ks++) {
            int kk = ks * 16;
            uint32_t ahf[4][4], alf[4][4], bhf[4][2], blf[4][2];
            #pragma unroll
            for (int ma = 0; ma < 4; ma++) {
                int rb = wm * 64 + ma * 16 + g;
                int cc = kk + tig * 2;
                ahf[ma][0] = ld32s(As  + rb * SQSTRIDE + cc);
                ahf[ma][1] = ld32s(As  + (rb + 8) * SQSTRIDE + cc);
                ahf[ma][2] = ld32s(As  + rb * SQSTRIDE + cc + 8);
                ahf[ma][3] = ld32s(As  + (rb + 8) * SQSTRIDE + cc + 8);
                alf[ma][0] = ld32s(Als + rb * SQSTRIDE + cc);
                alf[ma][1] = ld32s(Als + (rb + 8) * SQSTRIDE + cc);
                alf[ma][2] = ld32s(Als + rb * SQSTRIDE + cc + 8);
                alf[ma][3] = ld32s(Als + (rb + 8) * SQSTRIDE + cc + 8);
            }
            #pragma unroll
            for (int na = 0; na < 4; na++) {
                int nb = wn * 32 + na * 8 + g;
                int cc = kk + tig * 2;
                bhf[na][0] = ld32s(Bs  + nb * SQSTRIDE + cc);
                bhf[na][1] = ld32s(Bs  + nb * SQSTRIDE + cc + 8);
                blf[na][0] = ld32s(Bls + nb * SQSTRIDE + cc);
                blf[na][1] = ld32s(Bls + nb * SQSTRIDE + cc + 8);
            }
            #pragma unroll
            for (int ma = 0; ma < 4; ma++)
                #pragma unroll
                for (int na = 0; na < 4; na++) {
                    mma16816(acc[ma][na], ahf[ma], bhf[na]);
                    mma16816(acc[ma][na], ahf[ma], blf[na]);
                    mma16816(acc[ma][na], alf[ma], bhf[na]);
                }
        }
        __syncthreads();
        buf ^= 1;
    }

    // Epilogue: order-2 output, diag zero, x3 replication
    float* obase = out + (size_t)(v * 2 + 1) * OUT_G;
    #pragma unroll
    for (int ma = 0; ma < 4; ma++) {
        #pragma unroll
        for (int rr = 0; rr < 2; rr++) {
            int n = row0 + wm * 64 + ma * 16 + g + rr * 8;
            size_t orow = (size_t)(b * Nn + n) * (KTt * Nn);
            #pragma unroll
            for (int na = 0; na < 4; na++) {
                int col = col0 + wn * 32 + na * 8 + tig * 2;
                float v0 = acc[ma][na][rr * 2 + 0];
                float v1 = acc[ma][na][rr * 2 + 1];
                if (n == col)     v0 = 0.0f;
                if (n == col + 1) v1 = 0.0f;
                float2 o = make_float2(v0, v1);
                *(float2*)(obase + orow + col)          = o;
                *(float2*)(obase + orow + Nn + col)     = o;
                *(float2*)(obase + orow + 2 * Nn + col) = o;
            }
        }
    }
}

// ---------------------------------------------------------------------------
extern "C" void kernel_launch(void* const* d_in, const int* in_sizes, int n_in,
                              void* d_out, int out_size)
{
    const float* hist = (const float*)d_in[0];
    const float* embd = (const float*)d_in[1];
    const float* embu = (const float*)d_in[2];
    const float* tdf  = (const float*)d_in[3];
    const float* dwf  = (const float*)d_in[4];
    const float* m0   = (const float*)d_in[5];
    const float* m1   = (const float*)d_in[6];
    const float* W1   = (const float*)d_in[7];
    const float* b1   = (const float*)d_in[8];
    const float* gam  = (const float*)d_in[9];
    const float* bet  = (const float*)d_in[10];
    const float* mu   = (const float*)d_in[11];
    const float* var  = (const float*)d_in[12];
    const float* W2   = (const float*)d_in[13];
    const float* b2   = (const float*)d_in[14];
    const float* WQ   = (const float*)d_in[15];
    const float* WK   = (const float*)d_in[16];
    float* out = (float*)d_out;

    cudaFuncSetAttribute(qk_kernel, cudaFuncAttributeMaxDynamicSharedMemorySize,
                         QK_SMEM);
    cudaFuncSetAttribute(sq_mma_kernel, cudaFuncAttributeMaxDynamicSharedMemorySize,
                         SQ_SMEM);

    feat_kernel<<<dim3(Nn, Bb), 128>>>(hist, embd, embu, tdf, dwf,
                                       W1, b1, gam, bet, mu, var, W2, b2);
    qk_kernel<<<dim3(Nn / 128, Bb), 256, QK_SMEM>>>(WQ, WK);
    scores_kernel<<<dim3(16, 16, 4), 256>>>();
    softmax_kernel<<<dim3(Nn, 4), 256>>>(m0, m1, out);
    transpose_kernel<<<dim3(32, 32, 4), 256>>>();
    sq_mma_kernel<<<dim3(16, 16, 4), 256, SQ_SMEM>>>(out);
}

// round 4
// speedup vs baseline: 2.4815x; 1.3704x over previous
#include <cuda_runtime.h>
#include <cuda_fp16.h>
#include <math.h>
#include <cstdint>

// Problem constants
#define Bb  2
#define Ll  12
#define Nn  2048
#define Hh  64
#define NDe 32
#define TEe 10
#define Ff  148
#define F2  116
#define KTt 3

static const size_t OUT_G = (size_t)Bb * Nn * KTt * Nn;

// Scratch (allocation-free rule: device globals)
__device__ float g_feat[(size_t)Bb * Nn * Ff];
__device__ float g_Q[(size_t)4 * Nn * Hh];
__device__ float g_K[(size_t)4 * Nn * Hh];
__device__ float g_S[(size_t)4 * Nn * Nn];
__device__ __half g_Ah[(size_t)4 * Nn * Nn];  // A hi (fp16), row-major [m][k]
__device__ __half g_Al[(size_t)4 * Nn * Nn];  // A lo (fp16)
__device__ __half g_Bh[(size_t)4 * Nn * Nn];  // A^T hi, [n][k]

// ===========================================================================
// Baseline-ISA helpers (ptxas targets sm_103 — no sm_103a-only instructions)
// ===========================================================================
__device__ __forceinline__ void cpa16(uint32_t dst, const void* src) {
    asm volatile("cp.async.cg.shared.global [%0], [%1], 16;"
                 :: "r"(dst), "l"(src));
}
__device__ __forceinline__ void cpa_commit() {
    asm volatile("cp.async.commit_group;" ::: "memory");
}
template <int N> __device__ __forceinline__ void cpa_wait() {
    asm volatile("cp.async.wait_group %0;" :: "n"(N) : "memory");
}
__device__ __forceinline__ uint32_t s2u(const void* p) {
    uint32_t a;
    asm("{ .reg .u64 t; cvta.to.shared.u64 t, %1; cvt.u32.u64 %0, t; }"
        : "=r"(a) : "l"(p));
    return a;
}
__device__ __forceinline__ void mma16816h(float* d, const uint32_t* a,
                                          const uint32_t* b) {
    asm volatile(
        "mma.sync.aligned.m16n8k16.row.col.f32.f16.f16.f32 "
        "{%0,%1,%2,%3}, {%4,%5,%6,%7}, {%8,%9}, {%0,%1,%2,%3};"
        : "+f"(d[0]), "+f"(d[1]), "+f"(d[2]), "+f"(d[3])
        : "r"(a[0]), "r"(a[1]), "r"(a[2]), "r"(a[3]), "r"(b[0]), "r"(b[1]));
}
__device__ __forceinline__ void ldm4(uint32_t* r, uint32_t addr) {
    asm volatile("ldmatrix.sync.aligned.m8n8.x4.shared.b16 {%0,%1,%2,%3}, [%4];"
                 : "=r"(r[0]), "=r"(r[1]), "=r"(r[2]), "=r"(r[3]) : "r"(addr));
}

// ---------------------------------------------------------------------------
// Kernel 1: per-node feature prep (unchanged)
// ---------------------------------------------------------------------------
__global__ void __launch_bounds__(128) feat_kernel(
    const float* __restrict__ hist, const float* __restrict__ embd,
    const float* __restrict__ embu, const float* __restrict__ tdf,
    const float* __restrict__ dwf,
    const float* __restrict__ W1, const float* __restrict__ b1,
    const float* __restrict__ gamma, const float* __restrict__ beta,
    const float* __restrict__ mean, const float* __restrict__ var,
    const float* __restrict__ W2, const float* __restrict__ b2)
{
    int n = blockIdx.x, b = blockIdx.y, t = threadIdx.x;
    __shared__ float Xs[12];
    __shared__ float hs[128];
    __shared__ float fs[64];
    __shared__ float W1s[128 * 12];
    __shared__ float W2s[128 * 65];

    for (int i = t; i < 128 * 12; i += 128) W1s[i] = W1[i];
    for (int i = t; i < 64 * 128; i += 128) {
        int j = i >> 7, k = i & 127;
        W2s[k * 65 + j] = W2[i];
    }
    if (t < 12) Xs[t] = hist[(((size_t)b * Ll + t) * Nn + n) * 3];
    __syncthreads();

    {
        float acc = b1[t];
        #pragma unroll
        for (int l = 0; l < 12; l++) acc = fmaf(Xs[l], W1s[t * 12 + l], acc);
        acc = fmaxf(acc, 0.0f);
        acc = (acc - mean[t]) * (gamma[t] / sqrtf(var[t] + 1e-5f)) + beta[t];
        hs[t] = acc;
    }
    __syncthreads();

    if (t < 64) {
        float acc = b2[t];
        #pragma unroll 16
        for (int k = 0; k < 128; k++) acc = fmaf(hs[k], W2s[k * 65 + t], acc);
        fs[t] = acc;
    }
    __syncthreads();

    float* fr = g_feat + ((size_t)b * Nn + n) * Ff;
    size_t tbase = (((size_t)b * Ll + (Ll - 1)) * Nn + n) * TEe;
    for (int f = t; f < Ff; f += 128) {
        float val;
        if      (f < 64)  val = fs[f];
        else if (f < 74)  val = tdf[tbase + f - 64];
        else if (f < 84)  val = dwf[tbase + f - 74];
        else if (f < 116) val = embd[(size_t)n * NDe + (f - 84)];
        else              val = embu[(size_t)n * NDe + (f - 116)];
        fr[f] = val;
    }
}

// ---------------------------------------------------------------------------
// Kernel 2: Q/K projections (unchanged)
// ---------------------------------------------------------------------------
#define QK_SMEM ((Ff * 128 + 2 * F2 * 64) * (int)sizeof(float))

__global__ void __launch_bounds__(256) qk_kernel(
    const float* __restrict__ WQ, const float* __restrict__ WK)
{
    extern __shared__ float sm[];
    float* Fs  = sm;
    float* WQt = Fs + Ff * 128;
    float* WKt = WQt + F2 * 64;

    int node0 = blockIdx.x * 128;
    int b = blockIdx.y;
    int t = threadIdx.x;

    for (int i = t; i < 128 * Ff; i += 256) {
        int node = i / Ff, f = i - node * Ff;
        Fs[f * 128 + node] = g_feat[((size_t)b * Nn + node0 + node) * Ff + f];
    }
    for (int i = t; i < 64 * F2; i += 256) {
        int j = i / F2, f = i - j * F2;
        WQt[f * 64 + j] = WQ[i];
        WKt[f * 64 + j] = WK[i];
    }
    __syncthreads();

    int v = t >> 7, sel = (t >> 6) & 1, j = t & 63;
    const float* Wt = sel ? WKt : WQt;
    float* dst = (sel ? g_K : g_Q) + (size_t)(v * 2 + b) * Nn * Hh;
    int ebase = 84 + 32 * v;

    for (int nb = 0; nb < 128; nb += 8) {
        float acc[8] = {0, 0, 0, 0, 0, 0, 0, 0};
        for (int f = 0; f < 84; f++) {
            float w = Wt[f * 64 + j];
            #pragma unroll
            for (int u = 0; u < 8; u++)
                acc[u] = fmaf(Fs[f * 128 + nb + u], w, acc[u]);
        }
        #pragma unroll 8
        for (int e = 0; e < 32; e++) {
            float w = Wt[(84 + e) * 64 + j];
            #pragma unroll
            for (int u = 0; u < 8; u++)
                acc[u] = fmaf(Fs[(ebase + e) * 128 + nb + u], w, acc[u]);
        }
        #pragma unroll
        for (int u = 0; u < 8; u++)
            dst[(size_t)(node0 + nb + u) * Hh + j] = acc[u];
    }
}

// ---------------------------------------------------------------------------
// Kernel 3: scores = Q @ K^T * 1/sqrt(H) (unchanged)
// ---------------------------------------------------------------------------
__global__ void __launch_bounds__(256) scores_kernel()
{
    int c = blockIdx.z;
    const float* Q = g_Q + (size_t)c * Nn * Hh;
    const float* K = g_K + (size_t)c * Nn * Hh;
    float* S = g_S + (size_t)c * Nn * Nn;
    int row0 = blockIdx.y * 128, col0 = blockIdx.x * 128;

    __shared__ float Qs[32][128];
    __shared__ float Ks[32][128];

    int t = threadIdx.x;
    int tx = t & 15, ty = t >> 4;
    float acc[8][8] = {};

    for (int k0 = 0; k0 < Hh; k0 += 32) {
        #pragma unroll
        for (int it = 0; it < 4; it++) {
            int idx = t + it * 256;
            int r = idx >> 3;
            int kq = (idx & 7) * 4;
            float4 q4 = *(const float4*)(Q + (size_t)(row0 + r) * Hh + k0 + kq);
            Qs[kq + 0][r] = q4.x; Qs[kq + 1][r] = q4.y;
            Qs[kq + 2][r] = q4.z; Qs[kq + 3][r] = q4.w;
            float4 k4 = *(const float4*)(K + (size_t)(col0 + r) * Hh + k0 + kq);
            Ks[kq + 0][r] = k4.x; Ks[kq + 1][r] = k4.y;
            Ks[kq + 2][r] = k4.z; Ks[kq + 3][r] = k4.w;
        }
        __syncthreads();
        #pragma unroll
        for (int kk = 0; kk < 32; kk++) {
            float a[8], bb[8];
            *(float4*)&a[0]  = *(const float4*)&Qs[kk][ty * 8];
            *(float4*)&a[4]  = *(const float4*)&Qs[kk][ty * 8 + 4];
            *(float4*)&bb[0] = *(const float4*)&Ks[kk][tx * 8];
            *(float4*)&bb[4] = *(const float4*)&Ks[kk][tx * 8 + 4];
            #pragma unroll
            for (int i = 0; i < 8; i++)
                #pragma unroll
                for (int jj = 0; jj < 8; jj++)
                    acc[i][jj] = fmaf(a[i], bb[jj], acc[i][jj]);
        }
        __syncthreads();
    }

    #pragma unroll
    for (int i = 0; i < 8; i++) {
        int rr = row0 + ty * 8 + i;
        float4 o0 = make_float4(acc[i][0] * 0.125f, acc[i][1] * 0.125f,
                                acc[i][2] * 0.125f, acc[i][3] * 0.125f);
        float4 o1 = make_float4(acc[i][4] * 0.125f, acc[i][5] * 0.125f,
                                acc[i][6] * 0.125f, acc[i][7] * 0.125f);
        *(float4*)(S + (size_t)rr * Nn + col0 + tx * 8)     = o0;
        *(float4*)(S + (size_t)rr * Nn + col0 + tx * 8 + 4) = o1;
    }
}

// ---------------------------------------------------------------------------
// Kernel 4: fused masked softmax + normalize; emits order-1 output + hi/lo A
// (fp16 pair: A = Ah + Al exactly to ~2^-22)
// ---------------------------------------------------------------------------
__global__ void __launch_bounds__(256) softmax_kernel(
    const float* __restrict__ mask0, const float* __restrict__ mask1,
    float* __restrict__ out)
{
    int n = blockIdx.x, c = blockIdx.y, v = c >> 1, b = c & 1;
    int t = threadIdx.x;
    const float* srow = g_S + ((size_t)c * Nn + n) * Nn;
    const float* mrow = (v ? mask1 : mask0) + (size_t)n * Nn;

    float s[8];
    float lmax = -3.4e38f;
    #pragma unroll
    for (int i = 0; i < 8; i++) {
        s[i] = srow[t + i * 256];
        lmax = fmaxf(lmax, s[i]);
    }

    __shared__ float red[8];
    #pragma unroll
    for (int o = 16; o; o >>= 1)
        lmax = fmaxf(lmax, __shfl_xor_sync(0xffffffffu, lmax, o));
    if ((t & 31) == 0) red[t >> 5] = lmax;
    __syncthreads();
    float rmax = red[0];
    #pragma unroll
    for (int w = 1; w < 8; w++) rmax = fmaxf(rmax, red[w]);
    __syncthreads();

    float wv[8], lsum = 0.0f;
    #pragma unroll
    for (int i = 0; i < 8; i++) {
        wv[i] = (mrow[t + i * 256] + 1e-7f) * expf(s[i] - rmax);
        lsum += wv[i];
    }
    #pragma unroll
    for (int o = 16; o; o >>= 1)
        lsum += __shfl_xor_sync(0xffffffffu, lsum, o);
    if ((t & 31) == 0) red[t >> 5] = lsum;
    __syncthreads();
    float tot = 0.0f;
    #pragma unroll
    for (int w = 0; w < 8; w++) tot += red[w];
    float inv = 1.0f / tot;

    size_t abase = ((size_t)c * Nn + n) * Nn;
    float* orow = out + (size_t)(v * 2) * OUT_G + (size_t)(b * Nn + n) * KTt * Nn;
    #pragma unroll
    for (int i = 0; i < 8; i++) {
        int m = t + i * 256;
        float val = wv[i] * inv;
        __half h = __float2half_rn(val);
        float lo = val - __half2float(h);
        g_Ah[abase + m] = h;
        g_Al[abase + m] = __float2half_rn(lo);
        float ov = (m == n) ? 0.0f : val;
        orow[m] = ov;
        orow[Nn + m] = ov;
        orow[2 * Nn + m] = ov;
    }
}

// ---------------------------------------------------------------------------
// Kernel 4b: transpose Ah -> Bh (B[n][k] = A[k][n]); only hi needed for B
// ---------------------------------------------------------------------------
__global__ void __launch_bounds__(256) transpose_kernel()
{
    __shared__ __half th[64][65];
    int c = blockIdx.z;
    size_t cb = (size_t)c * Nn * Nn;
    int r0 = blockIdx.y * 64, c0 = blockIdx.x * 64;
    int t = threadIdx.x;
    for (int i = t; i < 64 * 64; i += 256) {
        int r = i >> 6, cc = i & 63;
        th[r][cc] = g_Ah[cb + (size_t)(r0 + r) * Nn + c0 + cc];
    }
    __syncthreads();
    for (int i = t; i < 64 * 64; i += 256) {
        int r = i >> 6, cc = i & 63;
        g_Bh[cb + (size_t)(c0 + r) * Nn + r0 + cc] = th[cc][r];
    }
}

// ---------------------------------------------------------------------------
// Kernel 5: C = A @ A via fp16 mma.sync, 2 passes: C = (Ah + Al) @ Bh.
// CTA 128x128, 8 warps (2x4) of 64x32, K-chunk 32, double-buffered cp.async,
// ldmatrix fragment loads. Epilogue: order-2 output, diag zero, x3 replicate.
// ---------------------------------------------------------------------------
#define SQSTRIDE 40                        // fp16 elems per smem row (32+8 pad)
#define ARR_B (128 * SQSTRIDE * 2)         // 10240 B per array
#define BUF_B (3 * ARR_B)                  // Ah, Al, Bh = 30720 B
#define SQ_SMEM (2 * BUF_B)                // 61440 B

__global__ void __launch_bounds__(256, 2) sq_mma_kernel(float* __restrict__ out)
{
    extern __shared__ char dsm[];
    int c = blockIdx.z, v = c >> 1, b = c & 1;
    int row0 = blockIdx.y * 128, col0 = blockIdx.x * 128;
    int t = threadIdx.x, wid = t >> 5, lane = t & 31;
    int g = lane >> 2, tig = lane & 3;
    int wm = wid >> 2, wn = wid & 3;           // warp tile: 64x32
    int lq = lane >> 3, lr = lane & 7;         // ldmatrix address decomposition

    size_t cb = (size_t)c * Nn * Nn;
    const __half* Ahg = g_Ah + cb;
    const __half* Alg = g_Al + cb;
    const __half* Bhg = g_Bh + cb;

    uint32_t sbase = s2u(dsm);
    float acc[4][4][4] = {};

    auto load_stage = [&](int s, int kc) {
        uint32_t sb = sbase + (uint32_t)s * BUF_B;
        int k0 = kc * 32;
        #pragma unroll
        for (int j = 0; j < 6; j++) {
            int idx = j * 256 + t;
            int arr = idx >> 9;                // 0..2
            int rem = idx & 511;
            int rr = rem >> 2, seg = rem & 3;
            const __half* base = (arr == 0) ? Ahg : (arr == 1) ? Alg : Bhg;
            int grow = ((arr < 2) ? row0 : col0) + rr;
            cpa16(sb + (uint32_t)arr * ARR_B + rr * (SQSTRIDE * 2) + seg * 16,
                  base + (size_t)grow * Nn + k0 + seg * 8);
        }
        cpa_commit();
    };

    load_stage(0, 0);

    int buf = 0;
    for (int kc = 0; kc < 64; kc++) {
        if (kc + 1 < 64) {
            load_stage(buf ^ 1, kc + 1);
            cpa_wait<1>();
        } else {
            cpa_wait<0>();
        }
        __syncthreads();

        uint32_t sb = sbase + (uint32_t)buf * BUF_B;
        uint32_t aAh = sb, aAl = sb + ARR_B, aBh = sb + 2 * ARR_B;

        #pragma unroll
        for (int ks = 0; ks < 2; ks++) {
            int kk = ks * 16;
            uint32_t ah[4][4], al[4][4], bh[4][2];
            #pragma unroll
            for (int ma = 0; ma < 4; ma++) {
                int row = wm * 64 + ma * 16 + (lq & 1) * 8 + lr;
                int col = kk + (lq >> 1) * 8;
                uint32_t off = (uint32_t)(row * SQSTRIDE + col) * 2;
                ldm4(ah[ma], aAh + off);
                ldm4(al[ma], aAl + off);
            }
            #pragma unroll
            for (int np = 0; np < 2; np++) {
                int nrow = wn * 32 + np * 16 + (lq >> 1) * 8 + lr;
                int col = kk + (lq & 1) * 8;
                uint32_t off = (uint32_t)(nrow * SQSTRIDE + col) * 2;
                uint32_t r4[4];
                ldm4(r4, aBh + off);
                bh[np * 2][0]     = r4[0]; bh[np * 2][1]     = r4[1];
                bh[np * 2 + 1][0] = r4[2]; bh[np * 2 + 1][1] = r4[3];
            }
            #pragma unroll
            for (int ma = 0; ma < 4; ma++)
                #pragma unroll
                for (int na = 0; na < 4; na++) {
                    mma16816h(acc[ma][na], ah[ma], bh[na]);
                    mma16816h(acc[ma][na], al[ma], bh[na]);
                }
        }
        __syncthreads();
        buf ^= 1;
    }

    // Epilogue: order-2 output, diag zero, x3 replication
    float* obase = out + (size_t)(v * 2 + 1) * OUT_G;
    #pragma unroll
    for (int ma = 0; ma < 4; ma++) {
        #pragma unroll
        for (int rr = 0; rr < 2; rr++) {
            int n = row0 + wm * 64 + ma * 16 + g + rr * 8;
            size_t orow = (size_t)(b * Nn + n) * (KTt * Nn);
            #pragma unroll
            for (int na = 0; na < 4; na++) {
                int col = col0 + wn * 32 + na * 8 + tig * 2;
                float v0 = acc[ma][na][rr * 2 + 0];
                float v1 = acc[ma][na][rr * 2 + 1];
                if (n == col)     v0 = 0.0f;
                if (n == col + 1) v1 = 0.0f;
                float2 o = make_float2(v0, v1);
                *(float2*)(obase + orow + col)          = o;
                *(float2*)(obase + orow + Nn + col)     = o;
                *(float2*)(obase + orow + 2 * Nn + col) = o;
            }
        }
    }
}

// ---------------------------------------------------------------------------
extern "C" void kernel_launch(void* const* d_in, const int* in_sizes, int n_in,
                              void* d_out, int out_size)
{
    const float* hist = (const float*)d_in[0];
    const float* embd = (const float*)d_in[1];
    const float* embu = (const float*)d_in[2];
    const float* tdf  = (const float*)d_in[3];
    const float* dwf  = (const float*)d_in[4];
    const float* m0   = (const float*)d_in[5];
    const float* m1   = (const float*)d_in[6];
    const float* W1   = (const float*)d_in[7];
    const float* b1   = (const float*)d_in[8];
    const float* gam  = (const float*)d_in[9];
    const float* bet  = (const float*)d_in[10];
    const float* mu   = (const float*)d_in[11];
    const float* var  = (const float*)d_in[12];
    const float* W2   = (const float*)d_in[13];
    const float* b2   = (const float*)d_in[14];
    const float* WQ   = (const float*)d_in[15];
    const float* WK   = (const float*)d_in[16];
    float* out = (float*)d_out;

    cudaFuncSetAttribute(qk_kernel, cudaFuncAttributeMaxDynamicSharedMemorySize,
                         QK_SMEM);
    cudaFuncSetAttribute(sq_mma_kernel, cudaFuncAttributeMaxDynamicSharedMemorySize,
                         SQ_SMEM);

    feat_kernel<<<dim3(Nn, Bb), 128>>>(hist, embd, embu, tdf, dwf,
                                       W1, b1, gam, bet, mu, var, W2, b2);
    qk_kernel<<<dim3(Nn / 128, Bb), 256, QK_SMEM>>>(WQ, WK);
    scores_kernel<<<dim3(16, 16, 4), 256>>>();
    softmax_kernel<<<dim3(Nn, 4), 256>>>(m0, m1, out);
    transpose_kernel<<<dim3(32, 32, 4), 256>>>();
    sq_mma_kernel<<<dim3(16, 16, 4), 256, SQ_SMEM>>>(out);
}

// round 5
// speedup vs baseline: 3.6323x; 1.4638x over previous
#include <cuda_runtime.h>
#include <cuda_fp16.h>
#include <math.h>
#include <cstdint>

// Problem constants
#define Bb  2
#define Ll  12
#define Nn  2048
#define Hh  64
#define NDe 32
#define TEe 10
#define Ff  148
#define F2  116
#define KTt 3

static const size_t OUT_G = (size_t)Bb * Nn * KTt * Nn;

// Scratch (allocation-free rule: device globals)
__device__ float g_feat[(size_t)Bb * Nn * Ff];
__device__ __half g_Qh[(size_t)4 * Nn * Hh];   // 0.125*Q hi (fp16)
__device__ __half g_Ql[(size_t)4 * Nn * Hh];   // 0.125*Q lo
__device__ __half g_Kh[(size_t)4 * Nn * Hh];   // K hi
__device__ __half g_Kl[(size_t)4 * Nn * Hh];   // K lo
__device__ float g_S[(size_t)4 * Nn * Nn];
__device__ __half g_Ah[(size_t)4 * Nn * Nn];   // A (fp16), row-major [m][k]
__device__ __half g_Bh[(size_t)4 * Nn * Nn];   // A^T (fp16), [n][k]

// ===========================================================================
// Baseline-ISA helpers (ptxas targets sm_103 — no sm_103a-only instructions)
// ===========================================================================
__device__ __forceinline__ void cpa16(uint32_t dst, const void* src) {
    asm volatile("cp.async.cg.shared.global [%0], [%1], 16;"
                 :: "r"(dst), "l"(src));
}
__device__ __forceinline__ void cpa_commit() {
    asm volatile("cp.async.commit_group;" ::: "memory");
}
template <int N> __device__ __forceinline__ void cpa_wait() {
    asm volatile("cp.async.wait_group %0;" :: "n"(N) : "memory");
}
__device__ __forceinline__ uint32_t s2u(const void* p) {
    uint32_t a;
    asm("{ .reg .u64 t; cvta.to.shared.u64 t, %1; cvt.u32.u64 %0, t; }"
        : "=r"(a) : "l"(p));
    return a;
}
__device__ __forceinline__ void mma16816h(float* d, const uint32_t* a,
                                          const uint32_t* b) {
    asm volatile(
        "mma.sync.aligned.m16n8k16.row.col.f32.f16.f16.f32 "
        "{%0,%1,%2,%3}, {%4,%5,%6,%7}, {%8,%9}, {%0,%1,%2,%3};"
        : "+f"(d[0]), "+f"(d[1]), "+f"(d[2]), "+f"(d[3])
        : "r"(a[0]), "r"(a[1]), "r"(a[2]), "r"(a[3]), "r"(b[0]), "r"(b[1]));
}
__device__ __forceinline__ void ldm4(uint32_t* r, uint32_t addr) {
    asm volatile("ldmatrix.sync.aligned.m8n8.x4.shared.b16 {%0,%1,%2,%3}, [%4];"
                 : "=r"(r[0]), "=r"(r[1]), "=r"(r[2]), "=r"(r[3]) : "r"(addr));
}

// ---------------------------------------------------------------------------
// Kernel 1: per-node feature prep (unchanged)
// ---------------------------------------------------------------------------
__global__ void __launch_bounds__(128) feat_kernel(
    const float* __restrict__ hist, const float* __restrict__ embd,
    const float* __restrict__ embu, const float* __restrict__ tdf,
    const float* __restrict__ dwf,
    const float* __restrict__ W1, const float* __restrict__ b1,
    const float* __restrict__ gamma, const float* __restrict__ beta,
    const float* __restrict__ mean, const float* __restrict__ var,
    const float* __restrict__ W2, const float* __restrict__ b2)
{
    int n = blockIdx.x, b = blockIdx.y, t = threadIdx.x;
    __shared__ float Xs[12];
    __shared__ float hs[128];
    __shared__ float fs[64];
    __shared__ float W1s[128 * 12];
    __shared__ float W2s[128 * 65];

    for (int i = t; i < 128 * 12; i += 128) W1s[i] = W1[i];
    for (int i = t; i < 64 * 128; i += 128) {
        int j = i >> 7, k = i & 127;
        W2s[k * 65 + j] = W2[i];
    }
    if (t < 12) Xs[t] = hist[(((size_t)b * Ll + t) * Nn + n) * 3];
    __syncthreads();

    {
        float acc = b1[t];
        #pragma unroll
        for (int l = 0; l < 12; l++) acc = fmaf(Xs[l], W1s[t * 12 + l], acc);
        acc = fmaxf(acc, 0.0f);
        acc = (acc - mean[t]) * (gamma[t] / sqrtf(var[t] + 1e-5f)) + beta[t];
        hs[t] = acc;
    }
    __syncthreads();

    if (t < 64) {
        float acc = b2[t];
        #pragma unroll 16
        for (int k = 0; k < 128; k++) acc = fmaf(hs[k], W2s[k * 65 + t], acc);
        fs[t] = acc;
    }
    __syncthreads();

    float* fr = g_feat + ((size_t)b * Nn + n) * Ff;
    size_t tbase = (((size_t)b * Ll + (Ll - 1)) * Nn + n) * TEe;
    for (int f = t; f < Ff; f += 128) {
        float val;
        if      (f < 64)  val = fs[f];
        else if (f < 74)  val = tdf[tbase + f - 64];
        else if (f < 84)  val = dwf[tbase + f - 74];
        else if (f < 116) val = embd[(size_t)n * NDe + (f - 84)];
        else              val = embu[(size_t)n * NDe + (f - 116)];
        fr[f] = val;
    }
}

// ---------------------------------------------------------------------------
// Kernel 2: Q/K projections -> fp16 hi/lo (Q pre-scaled by 1/sqrt(H))
// ---------------------------------------------------------------------------
#define QK_SMEM ((Ff * 128 + 2 * F2 * 64) * (int)sizeof(float))

__global__ void __launch_bounds__(256) qk_kernel(
    const float* __restrict__ WQ, const float* __restrict__ WK)
{
    extern __shared__ float sm[];
    float* Fs  = sm;
    float* WQt = Fs + Ff * 128;
    float* WKt = WQt + F2 * 64;

    int node0 = blockIdx.x * 128;
    int b = blockIdx.y;
    int t = threadIdx.x;

    for (int i = t; i < 128 * Ff; i += 256) {
        int node = i / Ff, f = i - node * Ff;
        Fs[f * 128 + node] = g_feat[((size_t)b * Nn + node0 + node) * Ff + f];
    }
    for (int i = t; i < 64 * F2; i += 256) {
        int j = i / F2, f = i - j * F2;
        WQt[f * 64 + j] = WQ[i];
        WKt[f * 64 + j] = WK[i];
    }
    __syncthreads();

    int v = t >> 7, sel = (t >> 6) & 1, j = t & 63;
    const float* Wt = sel ? WKt : WQt;
    __half* dh = (sel ? g_Kh : g_Qh) + (size_t)(v * 2 + b) * Nn * Hh;
    __half* dl = (sel ? g_Kl : g_Ql) + (size_t)(v * 2 + b) * Nn * Hh;
    float scale = sel ? 1.0f : 0.125f;
    int ebase = 84 + 32 * v;

    for (int nb = 0; nb < 128; nb += 8) {
        float acc[8] = {0, 0, 0, 0, 0, 0, 0, 0};
        for (int f = 0; f < 84; f++) {
            float w = Wt[f * 64 + j];
            #pragma unroll
            for (int u = 0; u < 8; u++)
                acc[u] = fmaf(Fs[f * 128 + nb + u], w, acc[u]);
        }
        #pragma unroll 8
        for (int e = 0; e < 32; e++) {
            float w = Wt[(84 + e) * 64 + j];
            #pragma unroll
            for (int u = 0; u < 8; u++)
                acc[u] = fmaf(Fs[(ebase + e) * 128 + nb + u], w, acc[u]);
        }
        #pragma unroll
        for (int u = 0; u < 8; u++) {
            float sv = acc[u] * scale;
            __half h = __float2half_rn(sv);
            float lo = sv - __half2float(h);
            size_t idx = (size_t)(node0 + nb + u) * Hh + j;
            dh[idx] = h;
            dl[idx] = __float2half_rn(lo);
        }
    }
}

// ---------------------------------------------------------------------------
// Kernel 3: scores = (0.125*Q) @ K^T via fp16 HMMA, 3-pass hi/lo (exact).
// CTA 128x128, 8 warps (2x4) of 64x32. K=64 loaded once (no pipeline).
// ---------------------------------------------------------------------------
#define SCSTRIDE 72                          // 64 + 8 pad halves
#define SC_ARR (128 * SCSTRIDE * 2)          // 18432 B
#define SC_SMEM (4 * SC_ARR)                 // Qh,Ql,Kh,Kl = 73728 B

__global__ void __launch_bounds__(256, 2) scores_mma_kernel()
{
    extern __shared__ char dsm[];
    int c = blockIdx.z;
    int row0 = blockIdx.y * 128, col0 = blockIdx.x * 128;
    int t = threadIdx.x, wid = t >> 5, lane = t & 31;
    int g = lane >> 2, tig = lane & 3;
    int wm = wid >> 2, wn = wid & 3;
    int lq = lane >> 3, lr = lane & 7;

    size_t qb = (size_t)c * Nn * Hh;
    uint32_t sb = s2u(dsm);
    uint32_t aQh = sb, aQl = sb + SC_ARR, aKh = sb + 2 * SC_ARR,
             aKl = sb + 3 * SC_ARR;

    // Load all 4 operand tiles: 128 rows x 64 halves each (8 x 16B per row)
    #pragma unroll
    for (int j = 0; j < 16; j++) {
        int idx = j * 256 + t;               // 0..4095
        int arr = idx >> 10;                 // 0..3
        int rem = idx & 1023;
        int rr = rem >> 3, seg = rem & 7;
        const __half* base = (arr == 0) ? g_Qh : (arr == 1) ? g_Ql
                           : (arr == 2) ? g_Kh : g_Kl;
        int grow = ((arr < 2) ? row0 : col0) + rr;
        cpa16(sb + (uint32_t)arr * SC_ARR + rr * (SCSTRIDE * 2) + seg * 16,
              base + qb + (size_t)grow * Hh + seg * 8);
    }
    cpa_commit();
    cpa_wait<0>();
    __syncthreads();

    float acc[4][4][4] = {};
    #pragma unroll
    for (int ks = 0; ks < 4; ks++) {
        int kk = ks * 16;
        uint32_t qh[4][4], ql[4][4], kh[4][2], kl[4][2];
        #pragma unroll
        for (int ma = 0; ma < 4; ma++) {
            int row = wm * 64 + ma * 16 + (lq & 1) * 8 + lr;
            int col = kk + (lq >> 1) * 8;
            uint32_t off = (uint32_t)(row * SCSTRIDE + col) * 2;
            ldm4(qh[ma], aQh + off);
            ldm4(ql[ma], aQl + off);
        }
        #pragma unroll
        for (int np = 0; np < 2; np++) {
            int nrow = wn * 32 + np * 16 + (lq >> 1) * 8 + lr;
            int col = kk + (lq & 1) * 8;
            uint32_t off = (uint32_t)(nrow * SCSTRIDE + col) * 2;
            uint32_t r4[4];
            ldm4(r4, aKh + off);
            kh[np * 2][0] = r4[0]; kh[np * 2][1] = r4[1];
            kh[np * 2 + 1][0] = r4[2]; kh[np * 2 + 1][1] = r4[3];
            ldm4(r4, aKl + off);
            kl[np * 2][0] = r4[0]; kl[np * 2][1] = r4[1];
            kl[np * 2 + 1][0] = r4[2]; kl[np * 2 + 1][1] = r4[3];
        }
        #pragma unroll
        for (int ma = 0; ma < 4; ma++)
            #pragma unroll
            for (int na = 0; na < 4; na++) {
                mma16816h(acc[ma][na], qh[ma], kh[na]);
                mma16816h(acc[ma][na], qh[ma], kl[na]);
                mma16816h(acc[ma][na], ql[ma], kh[na]);
            }
    }

    float* S = g_S + (size_t)c * Nn * Nn;
    #pragma unroll
    for (int ma = 0; ma < 4; ma++)
        #pragma unroll
        for (int rr = 0; rr < 2; rr++) {
            int n = row0 + wm * 64 + ma * 16 + g + rr * 8;
            #pragma unroll
            for (int na = 0; na < 4; na++) {
                int col = col0 + wn * 32 + na * 8 + tig * 2;
                *(float2*)(S + (size_t)n * Nn + col) =
                    make_float2(acc[ma][na][rr * 2 + 0], acc[ma][na][rr * 2 + 1]);
            }
        }
}

// ---------------------------------------------------------------------------
// Kernel 4: fused masked softmax + normalize; emits order-1 output + fp16 A
// ---------------------------------------------------------------------------
__global__ void __launch_bounds__(256) softmax_kernel(
    const float* __restrict__ mask0, const float* __restrict__ mask1,
    float* __restrict__ out)
{
    int n = blockIdx.x, c = blockIdx.y, v = c >> 1, b = c & 1;
    int t = threadIdx.x;
    const float* srow = g_S + ((size_t)c * Nn + n) * Nn;
    const float* mrow = (v ? mask1 : mask0) + (size_t)n * Nn;

    float s[8];
    float lmax = -3.4e38f;
    #pragma unroll
    for (int i = 0; i < 8; i++) {
        s[i] = srow[t + i * 256];
        lmax = fmaxf(lmax, s[i]);
    }

    __shared__ float red[8];
    #pragma unroll
    for (int o = 16; o; o >>= 1)
        lmax = fmaxf(lmax, __shfl_xor_sync(0xffffffffu, lmax, o));
    if ((t & 31) == 0) red[t >> 5] = lmax;
    __syncthreads();
    float rmax = red[0];
    #pragma unroll
    for (int w = 1; w < 8; w++) rmax = fmaxf(rmax, red[w]);
    __syncthreads();

    float wv[8], lsum = 0.0f;
    #pragma unroll
    for (int i = 0; i < 8; i++) {
        wv[i] = (mrow[t + i * 256] + 1e-7f) * expf(s[i] - rmax);
        lsum += wv[i];
    }
    #pragma unroll
    for (int o = 16; o; o >>= 1)
        lsum += __shfl_xor_sync(0xffffffffu, lsum, o);
    if ((t & 31) == 0) red[t >> 5] = lsum;
    __syncthreads();
    float tot = 0.0f;
    #pragma unroll
    for (int w = 0; w < 8; w++) tot += red[w];
    float inv = 1.0f / tot;

    size_t abase = ((size_t)c * Nn + n) * Nn;
    float* orow = out + (size_t)(v * 2) * OUT_G + (size_t)(b * Nn + n) * KTt * Nn;
    #pragma unroll
    for (int i = 0; i < 8; i++) {
        int m = t + i * 256;
        float val = wv[i] * inv;
        g_Ah[abase + m] = __float2half_rn(val);
        float ov = (m == n) ? 0.0f : val;
        orow[m] = ov;
        orow[Nn + m] = ov;
        orow[2 * Nn + m] = ov;
    }
}

// ---------------------------------------------------------------------------
// Kernel 4b: transpose Ah -> Bh (B[n][k] = A[k][n])
// ---------------------------------------------------------------------------
__global__ void __launch_bounds__(256) transpose_kernel()
{
    __shared__ __half th[64][65];
    int c = blockIdx.z;
    size_t cb = (size_t)c * Nn * Nn;
    int r0 = blockIdx.y * 64, c0 = blockIdx.x * 64;
    int t = threadIdx.x;
    for (int i = t; i < 64 * 64; i += 256) {
        int r = i >> 6, cc = i & 63;
        th[r][cc] = g_Ah[cb + (size_t)(r0 + r) * Nn + c0 + cc];
    }
    __syncthreads();
    for (int i = t; i < 64 * 64; i += 256) {
        int r = i >> 6, cc = i & 63;
        g_Bh[cb + (size_t)(c0 + r) * Nn + r0 + cc] = th[cc][r];
    }
}

// ---------------------------------------------------------------------------
// Kernel 5: C = A @ A via fp16 mma.sync, single pass (Ah @ Bh).
// CTA 128x128, 8 warps of 64x32, K-chunk 32, double-buffered cp.async.
// Epilogue: order-2 output, diag zero, x3 replication.
// ---------------------------------------------------------------------------
#define SQSTRIDE 40
#define ARR_B (128 * SQSTRIDE * 2)           // 10240 B
#define BUF_B (2 * ARR_B)                    // Ah, Bh = 20480 B
#define SQ_SMEM (2 * BUF_B)                  // 40960 B

__global__ void __launch_bounds__(256, 2) sq_mma_kernel(float* __restrict__ out)
{
    extern __shared__ char dsm[];
    int c = blockIdx.z, v = c >> 1, b = c & 1;
    int row0 = blockIdx.y * 128, col0 = blockIdx.x * 128;
    int t = threadIdx.x, wid = t >> 5, lane = t & 31;
    int g = lane >> 2, tig = lane & 3;
    int wm = wid >> 2, wn = wid & 3;
    int lq = lane >> 3, lr = lane & 7;

    size_t cb = (size_t)c * Nn * Nn;
    const __half* Ahg = g_Ah + cb;
    const __half* Bhg = g_Bh + cb;

    uint32_t sbase = s2u(dsm);
    float acc[4][4][4] = {};

    auto load_stage = [&](int s, int kc) {
        uint32_t sb = sbase + (uint32_t)s * BUF_B;
        int k0 = kc * 32;
        #pragma unroll
        for (int j = 0; j < 4; j++) {
            int idx = j * 256 + t;           // 0..1023
            int arr = idx >> 9;              // 0..1
            int rem = idx & 511;
            int rr = rem >> 2, seg = rem & 3;
            const __half* base = arr ? Bhg : Ahg;
            int grow = (arr ? col0 : row0) + rr;
            cpa16(sb + (uint32_t)arr * ARR_B + rr * (SQSTRIDE * 2) + seg * 16,
                  base + (size_t)grow * Nn + k0 + seg * 8);
        }
        cpa_commit();
    };

    load_stage(0, 0);

    int buf = 0;
    for (int kc = 0; kc < 64; kc++) {
        if (kc + 1 < 64) {
            load_stage(buf ^ 1, kc + 1);
            cpa_wait<1>();
        } else {
            cpa_wait<0>();
        }
        __syncthreads();

        uint32_t sb = sbase + (uint32_t)buf * BUF_B;
        uint32_t aAh = sb, aBh = sb + ARR_B;

        #pragma unroll
        for (int ks = 0; ks < 2; ks++) {
            int kk = ks * 16;
            uint32_t ah[4][4], bh[4][2];
            #pragma unroll
            for (int ma = 0; ma < 4; ma++) {
                int row = wm * 64 + ma * 16 + (lq & 1) * 8 + lr;
                int col = kk + (lq >> 1) * 8;
                ldm4(ah[ma], aAh + (uint32_t)(row * SQSTRIDE + col) * 2);
            }
            #pragma unroll
            for (int np = 0; np < 2; np++) {
                int nrow = wn * 32 + np * 16 + (lq >> 1) * 8 + lr;
                int col = kk + (lq & 1) * 8;
                uint32_t r4[4];
                ldm4(r4, aBh + (uint32_t)(nrow * SQSTRIDE + col) * 2);
                bh[np * 2][0] = r4[0]; bh[np * 2][1] = r4[1];
                bh[np * 2 + 1][0] = r4[2]; bh[np * 2 + 1][1] = r4[3];
            }
            #pragma unroll
            for (int ma = 0; ma < 4; ma++)
                #pragma unroll
                for (int na = 0; na < 4; na++)
                    mma16816h(acc[ma][na], ah[ma], bh[na]);
        }
        __syncthreads();
        buf ^= 1;
    }

    // Epilogue: order-2 output, diag zero, x3 replication
    float* obase = out + (size_t)(v * 2 + 1) * OUT_G;
    #pragma unroll
    for (int ma = 0; ma < 4; ma++) {
        #pragma unroll
        for (int rr = 0; rr < 2; rr++) {
            int n = row0 + wm * 64 + ma * 16 + g + rr * 8;
            size_t orow = (size_t)(b * Nn + n) * (KTt * Nn);
            #pragma unroll
            for (int na = 0; na < 4; na++) {
                int col = col0 + wn * 32 + na * 8 + tig * 2;
                float v0 = acc[ma][na][rr * 2 + 0];
                float v1 = acc[ma][na][rr * 2 + 1];
                if (n == col)     v0 = 0.0f;
                if (n == col + 1) v1 = 0.0f;
                float2 o = make_float2(v0, v1);
                *(float2*)(obase + orow + col)          = o;
                *(float2*)(obase + orow + Nn + col)     = o;
                *(float2*)(obase + orow + 2 * Nn + col) = o;
            }
        }
    }
}

// ---------------------------------------------------------------------------
extern "C" void kernel_launch(void* const* d_in, const int* in_sizes, int n_in,
                              void* d_out, int out_size)
{
    const float* hist = (const float*)d_in[0];
    const float* embd = (const float*)d_in[1];
    const float* embu = (const float*)d_in[2];
    const float* tdf  = (const float*)d_in[3];
    const float* dwf  = (const float*)d_in[4];
    const float* m0   = (const float*)d_in[5];
    const float* m1   = (const float*)d_in[6];
    const float* W1   = (const float*)d_in[7];
    const float* b1   = (const float*)d_in[8];
    const float* gam  = (const float*)d_in[9];
    const float* bet  = (const float*)d_in[10];
    const float* mu   = (const float*)d_in[11];
    const float* var  = (const float*)d_in[12];
    const float* W2   = (const float*)d_in[13];
    const float* b2   = (const float*)d_in[14];
    const float* WQ   = (const float*)d_in[15];
    const float* WK   = (const float*)d_in[16];
    float* out = (float*)d_out;

    cudaFuncSetAttribute(qk_kernel, cudaFuncAttributeMaxDynamicSharedMemorySize,
                         QK_SMEM);
    cudaFuncSetAttribute(scores_mma_kernel,
                         cudaFuncAttributeMaxDynamicSharedMemorySize, SC_SMEM);
    cudaFuncSetAttribute(sq_mma_kernel, cudaFuncAttributeMaxDynamicSharedMemorySize,
                         SQ_SMEM);

    feat_kernel<<<dim3(Nn, Bb), 128>>>(hist, embd, embu, tdf, dwf,
                                       W1, b1, gam, bet, mu, var, W2, b2);
    qk_kernel<<<dim3(Nn / 128, Bb), 256, QK_SMEM>>>(WQ, WK);
    scores_mma_kernel<<<dim3(16, 16, 4), 256, SC_SMEM>>>();
    softmax_kernel<<<dim3(Nn, 4), 256>>>(m0, m1, out);
    transpose_kernel<<<dim3(32, 32, 4), 256>>>();
    sq_mma_kernel<<<dim3(16, 16, 4), 256, SQ_SMEM>>>(out);
}

// round 6
// speedup vs baseline: 4.2412x; 1.1676x over previous
#include <cuda_runtime.h>
#include <cuda_fp16.h>
#include <math.h>
#include <cstdint>

// Problem constants
#define Bb  2
#define Ll  12
#define Nn  2048
#define Hh  64
#define NDe 32
#define TEe 10
#define Ff  148
#define F2  116
#define KTt 3

static const size_t OUT_G = (size_t)Bb * Nn * KTt * Nn;

// Scratch (allocation-free rule: device globals)
__device__ float g_feat[(size_t)Bb * Nn * Ff];
__device__ __half g_Qh[(size_t)4 * Nn * Hh];   // 0.125*Q hi (fp16)
__device__ __half g_Ql[(size_t)4 * Nn * Hh];   // 0.125*Q lo
__device__ __half g_Kh[(size_t)4 * Nn * Hh];   // K hi
__device__ __half g_Kl[(size_t)4 * Nn * Hh];   // K lo
__device__ float g_S[(size_t)4 * Nn * Nn];
__device__ __half g_Ah[(size_t)4 * Nn * Nn];   // A (fp16), row-major [m][k]

// ===========================================================================
// Baseline-ISA helpers (ptxas targets sm_103 — no sm_103a-only instructions)
// ===========================================================================
__device__ __forceinline__ void cpa16(uint32_t dst, const void* src) {
    asm volatile("cp.async.cg.shared.global [%0], [%1], 16;"
                 :: "r"(dst), "l"(src));
}
__device__ __forceinline__ void cpa_commit() {
    asm volatile("cp.async.commit_group;" ::: "memory");
}
template <int N> __device__ __forceinline__ void cpa_wait() {
    asm volatile("cp.async.wait_group %0;" :: "n"(N) : "memory");
}
__device__ __forceinline__ uint32_t s2u(const void* p) {
    uint32_t a;
    asm("{ .reg .u64 t; cvta.to.shared.u64 t, %1; cvt.u32.u64 %0, t; }"
        : "=r"(a) : "l"(p));
    return a;
}
__device__ __forceinline__ void mma16816h(float* d, const uint32_t* a,
                                          const uint32_t* b) {
    asm volatile(
        "mma.sync.aligned.m16n8k16.row.col.f32.f16.f16.f32 "
        "{%0,%1,%2,%3}, {%4,%5,%6,%7}, {%8,%9}, {%0,%1,%2,%3};"
        : "+f"(d[0]), "+f"(d[1]), "+f"(d[2]), "+f"(d[3])
        : "r"(a[0]), "r"(a[1]), "r"(a[2]), "r"(a[3]), "r"(b[0]), "r"(b[1]));
}
__device__ __forceinline__ void ldm4(uint32_t* r, uint32_t addr) {
    asm volatile("ldmatrix.sync.aligned.m8n8.x4.shared.b16 {%0,%1,%2,%3}, [%4];"
                 : "=r"(r[0]), "=r"(r[1]), "=r"(r[2]), "=r"(r[3]) : "r"(addr));
}
__device__ __forceinline__ void ldm4t(uint32_t* r, uint32_t addr) {
    asm volatile("ldmatrix.sync.aligned.m8n8.x4.trans.shared.b16 {%0,%1,%2,%3}, [%4];"
                 : "=r"(r[0]), "=r"(r[1]), "=r"(r[2]), "=r"(r[3]) : "r"(addr));
}

// ---------------------------------------------------------------------------
// Kernel 1: per-node feature prep (unchanged)
// ---------------------------------------------------------------------------
__global__ void __launch_bounds__(128) feat_kernel(
    const float* __restrict__ hist, const float* __restrict__ embd,
    const float* __restrict__ embu, const float* __restrict__ tdf,
    const float* __restrict__ dwf,
    const float* __restrict__ W1, const float* __restrict__ b1,
    const float* __restrict__ gamma, const float* __restrict__ beta,
    const float* __restrict__ mean, const float* __restrict__ var,
    const float* __restrict__ W2, const float* __restrict__ b2)
{
    int n = blockIdx.x, b = blockIdx.y, t = threadIdx.x;
    __shared__ float Xs[12];
    __shared__ float hs[128];
    __shared__ float fs[64];
    __shared__ float W1s[128 * 12];
    __shared__ float W2s[128 * 65];

    for (int i = t; i < 128 * 12; i += 128) W1s[i] = W1[i];
    for (int i = t; i < 64 * 128; i += 128) {
        int j = i >> 7, k = i & 127;
        W2s[k * 65 + j] = W2[i];
    }
    if (t < 12) Xs[t] = hist[(((size_t)b * Ll + t) * Nn + n) * 3];
    __syncthreads();

    {
        float acc = b1[t];
        #pragma unroll
        for (int l = 0; l < 12; l++) acc = fmaf(Xs[l], W1s[t * 12 + l], acc);
        acc = fmaxf(acc, 0.0f);
        acc = (acc - mean[t]) * (gamma[t] / sqrtf(var[t] + 1e-5f)) + beta[t];
        hs[t] = acc;
    }
    __syncthreads();

    if (t < 64) {
        float acc = b2[t];
        #pragma unroll 16
        for (int k = 0; k < 128; k++) acc = fmaf(hs[k], W2s[k * 65 + t], acc);
        fs[t] = acc;
    }
    __syncthreads();

    float* fr = g_feat + ((size_t)b * Nn + n) * Ff;
    size_t tbase = (((size_t)b * Ll + (Ll - 1)) * Nn + n) * TEe;
    for (int f = t; f < Ff; f += 128) {
        float val;
        if      (f < 64)  val = fs[f];
        else if (f < 74)  val = tdf[tbase + f - 64];
        else if (f < 84)  val = dwf[tbase + f - 74];
        else if (f < 116) val = embd[(size_t)n * NDe + (f - 84)];
        else              val = embu[(size_t)n * NDe + (f - 116)];
        fr[f] = val;
    }
}

// ---------------------------------------------------------------------------
// Kernel 2: Q/K projections -> fp16 hi/lo (Q pre-scaled by 1/sqrt(H))
// ---------------------------------------------------------------------------
#define QK_SMEM ((Ff * 128 + 2 * F2 * 64) * (int)sizeof(float))

__global__ void __launch_bounds__(256) qk_kernel(
    const float* __restrict__ WQ, const float* __restrict__ WK)
{
    extern __shared__ float sm[];
    float* Fs  = sm;
    float* WQt = Fs + Ff * 128;
    float* WKt = WQt + F2 * 64;

    int node0 = blockIdx.x * 128;
    int b = blockIdx.y;
    int t = threadIdx.x;

    for (int i = t; i < 128 * Ff; i += 256) {
        int node = i / Ff, f = i - node * Ff;
        Fs[f * 128 + node] = g_feat[((size_t)b * Nn + node0 + node) * Ff + f];
    }
    for (int i = t; i < 64 * F2; i += 256) {
        int j = i / F2, f = i - j * F2;
        WQt[f * 64 + j] = WQ[i];
        WKt[f * 64 + j] = WK[i];
    }
    __syncthreads();

    int v = t >> 7, sel = (t >> 6) & 1, j = t & 63;
    const float* Wt = sel ? WKt : WQt;
    __half* dh = (sel ? g_Kh : g_Qh) + (size_t)(v * 2 + b) * Nn * Hh;
    __half* dl = (sel ? g_Kl : g_Ql) + (size_t)(v * 2 + b) * Nn * Hh;
    float scale = sel ? 1.0f : 0.125f;
    int ebase = 84 + 32 * v;

    for (int nb = 0; nb < 128; nb += 8) {
        float acc[8] = {0, 0, 0, 0, 0, 0, 0, 0};
        for (int f = 0; f < 84; f++) {
            float w = Wt[f * 64 + j];
            #pragma unroll
            for (int u = 0; u < 8; u++)
                acc[u] = fmaf(Fs[f * 128 + nb + u], w, acc[u]);
        }
        #pragma unroll 8
        for (int e = 0; e < 32; e++) {
            float w = Wt[(84 + e) * 64 + j];
            #pragma unroll
            for (int u = 0; u < 8; u++)
                acc[u] = fmaf(Fs[(ebase + e) * 128 + nb + u], w, acc[u]);
        }
        #pragma unroll
        for (int u = 0; u < 8; u++) {
            float sv = acc[u] * scale;
            __half h = __float2half_rn(sv);
            float lo = sv - __half2float(h);
            size_t idx = (size_t)(node0 + nb + u) * Hh + j;
            dh[idx] = h;
            dl[idx] = __float2half_rn(lo);
        }
    }
}

// ---------------------------------------------------------------------------
// Kernel 3: scores = (0.125*Q) @ K^T via fp16 HMMA, 3-pass hi/lo (exact).
// ---------------------------------------------------------------------------
#define SCSTRIDE 72
#define SC_ARR (128 * SCSTRIDE * 2)
#define SC_SMEM (4 * SC_ARR)

__global__ void __launch_bounds__(256, 2) scores_mma_kernel(int cbase)
{
    extern __shared__ char dsm[];
    int c = cbase + blockIdx.z;
    int row0 = blockIdx.y * 128, col0 = blockIdx.x * 128;
    int t = threadIdx.x, wid = t >> 5, lane = t & 31;
    int g = lane >> 2, tig = lane & 3;
    int wm = wid >> 2, wn = wid & 3;
    int lq = lane >> 3, lr = lane & 7;

    size_t qb = (size_t)c * Nn * Hh;
    uint32_t sb = s2u(dsm);
    uint32_t aQh = sb, aQl = sb + SC_ARR, aKh = sb + 2 * SC_ARR,
             aKl = sb + 3 * SC_ARR;

    #pragma unroll
    for (int j = 0; j < 16; j++) {
        int idx = j * 256 + t;
        int arr = idx >> 10;
        int rem = idx & 1023;
        int rr = rem >> 3, seg = rem & 7;
        const __half* base = (arr == 0) ? g_Qh : (arr == 1) ? g_Ql
                           : (arr == 2) ? g_Kh : g_Kl;
        int grow = ((arr < 2) ? row0 : col0) + rr;
        cpa16(sb + (uint32_t)arr * SC_ARR + rr * (SCSTRIDE * 2) + seg * 16,
              base + qb + (size_t)grow * Hh + seg * 8);
    }
    cpa_commit();
    cpa_wait<0>();
    __syncthreads();

    float acc[4][4][4] = {};
    #pragma unroll
    for (int ks = 0; ks < 4; ks++) {
        int kk = ks * 16;
        uint32_t qh[4][4], ql[4][4], kh[4][2], kl[4][2];
        #pragma unroll
        for (int ma = 0; ma < 4; ma++) {
            int row = wm * 64 + ma * 16 + (lq & 1) * 8 + lr;
            int col = kk + (lq >> 1) * 8;
            uint32_t off = (uint32_t)(row * SCSTRIDE + col) * 2;
            ldm4(qh[ma], aQh + off);
            ldm4(ql[ma], aQl + off);
        }
        #pragma unroll
        for (int np = 0; np < 2; np++) {
            int nrow = wn * 32 + np * 16 + (lq >> 1) * 8 + lr;
            int col = kk + (lq & 1) * 8;
            uint32_t off = (uint32_t)(nrow * SCSTRIDE + col) * 2;
            uint32_t r4[4];
            ldm4(r4, aKh + off);
            kh[np * 2][0] = r4[0]; kh[np * 2][1] = r4[1];
            kh[np * 2 + 1][0] = r4[2]; kh[np * 2 + 1][1] = r4[3];
            ldm4(r4, aKl + off);
            kl[np * 2][0] = r4[0]; kl[np * 2][1] = r4[1];
            kl[np * 2 + 1][0] = r4[2]; kl[np * 2 + 1][1] = r4[3];
        }
        #pragma unroll
        for (int ma = 0; ma < 4; ma++)
            #pragma unroll
            for (int na = 0; na < 4; na++) {
                mma16816h(acc[ma][na], qh[ma], kh[na]);
                mma16816h(acc[ma][na], qh[ma], kl[na]);
                mma16816h(acc[ma][na], ql[ma], kh[na]);
            }
    }

    float* S = g_S + (size_t)c * Nn * Nn;
    #pragma unroll
    for (int ma = 0; ma < 4; ma++)
        #pragma unroll
        for (int rr = 0; rr < 2; rr++) {
            int n = row0 + wm * 64 + ma * 16 + g + rr * 8;
            #pragma unroll
            for (int na = 0; na < 4; na++) {
                int col = col0 + wn * 32 + na * 8 + tig * 2;
                *(float2*)(S + (size_t)n * Nn + col) =
                    make_float2(acc[ma][na][rr * 2 + 0], acc[ma][na][rr * 2 + 1]);
            }
        }
}

// ---------------------------------------------------------------------------
// Kernel 4: fused masked softmax + normalize; emits order-1 output + fp16 A
// ---------------------------------------------------------------------------
__global__ void __launch_bounds__(256) softmax_kernel(
    const float* __restrict__ mask0, const float* __restrict__ mask1,
    float* __restrict__ out, int cbase)
{
    int n = blockIdx.x, c = cbase + blockIdx.y, v = c >> 1, b = c & 1;
    int t = threadIdx.x;
    const float* srow = g_S + ((size_t)c * Nn + n) * Nn;
    const float* mrow = (v ? mask1 : mask0) + (size_t)n * Nn;

    float s[8];
    float lmax = -3.4e38f;
    #pragma unroll
    for (int i = 0; i < 8; i++) {
        s[i] = srow[t + i * 256];
        lmax = fmaxf(lmax, s[i]);
    }

    __shared__ float red[8];
    #pragma unroll
    for (int o = 16; o; o >>= 1)
        lmax = fmaxf(lmax, __shfl_xor_sync(0xffffffffu, lmax, o));
    if ((t & 31) == 0) red[t >> 5] = lmax;
    __syncthreads();
    float rmax = red[0];
    #pragma unroll
    for (int w = 1; w < 8; w++) rmax = fmaxf(rmax, red[w]);
    __syncthreads();

    float wv[8], lsum = 0.0f;
    #pragma unroll
    for (int i = 0; i < 8; i++) {
        wv[i] = (mrow[t + i * 256] + 1e-7f) * expf(s[i] - rmax);
        lsum += wv[i];
    }
    #pragma unroll
    for (int o = 16; o; o >>= 1)
        lsum += __shfl_xor_sync(0xffffffffu, lsum, o);
    if ((t & 31) == 0) red[t >> 5] = lsum;
    __syncthreads();
    float tot = 0.0f;
    #pragma unroll
    for (int w = 0; w < 8; w++) tot += red[w];
    float inv = 1.0f / tot;

    size_t abase = ((size_t)c * Nn + n) * Nn;
    float* orow = out + (size_t)(v * 2) * OUT_G + (size_t)(b * Nn + n) * KTt * Nn;
    #pragma unroll
    for (int i = 0; i < 8; i++) {
        int m = t + i * 256;
        float val = wv[i] * inv;
        g_Ah[abase + m] = __float2half_rn(val);
        float ov = (m == n) ? 0.0f : val;
        orow[m] = ov;
        orow[Nn + m] = ov;
        orow[2 * Nn + m] = ov;
    }
}

// ---------------------------------------------------------------------------
// Kernel 5: C = A @ A via fp16 mma.sync, single pass. B operand loaded from
// A's own row-major layout via ldmatrix.trans (no transpose kernel needed).
// CTA 128x128, 8 warps of 64x32, K-chunk 32, double-buffered cp.async.
// ---------------------------------------------------------------------------
#define ASTRIDE 40                           // A tile: 128 x 32 halves (+8 pad)
#define BSTRIDE 136                          // B tile: 32 x 128 halves (+8 pad)
#define A_B (128 * ASTRIDE * 2)              // 10240 B
#define B_B (32 * BSTRIDE * 2)               // 8704 B
#define BUF_B (A_B + B_B)                    // 18944 B
#define SQ_SMEM (2 * BUF_B)                  // 37888 B

__global__ void __launch_bounds__(256, 2) sq_mma_kernel(float* __restrict__ out,
                                                        int cbase)
{
    extern __shared__ char dsm[];
    int c = cbase + blockIdx.z, v = c >> 1, b = c & 1;
    int row0 = blockIdx.y * 128, col0 = blockIdx.x * 128;
    int t = threadIdx.x, wid = t >> 5, lane = t & 31;
    int g = lane >> 2, tig = lane & 3;
    int wm = wid >> 2, wn = wid & 3;
    int lq = lane >> 3, lr = lane & 7;

    size_t cb = (size_t)c * Nn * Nn;
    const __half* Ahg = g_Ah + cb;

    uint32_t sbase = s2u(dsm);
    float acc[4][4][4] = {};

    auto load_stage = [&](int s, int kc) {
        uint32_t sb = sbase + (uint32_t)s * BUF_B;
        int k0 = kc * 32;
        #pragma unroll
        for (int j = 0; j < 2; j++) {        // A tile: rows of the C block
            int idx = j * 256 + t;           // 0..511
            int rr = idx >> 2, seg = idx & 3;
            cpa16(sb + rr * (ASTRIDE * 2) + seg * 16,
                  Ahg + (size_t)(row0 + rr) * Nn + k0 + seg * 8);
        }
        #pragma unroll
        for (int j = 0; j < 2; j++) {        // B tile: A[k0..k0+31][col0..col0+127]
            int idx = j * 256 + t;           // 0..511
            int rr = idx >> 4, seg = idx & 15;
            cpa16(sb + A_B + rr * (BSTRIDE * 2) + seg * 16,
                  Ahg + (size_t)(k0 + rr) * Nn + col0 + seg * 8);
        }
        cpa_commit();
    };

    load_stage(0, 0);

    int buf = 0;
    for (int kc = 0; kc < 64; kc++) {
        if (kc + 1 < 64) {
            load_stage(buf ^ 1, kc + 1);
            cpa_wait<1>();
        } else {
            cpa_wait<0>();
        }
        __syncthreads();

        uint32_t sb = sbase + (uint32_t)buf * BUF_B;
        uint32_t aA = sb, aB = sb + A_B;

        #pragma unroll
        for (int ks = 0; ks < 2; ks++) {
            int kk = ks * 16;
            uint32_t ah[4][4], bh[4][2];
            #pragma unroll
            for (int ma = 0; ma < 4; ma++) {
                int row = wm * 64 + ma * 16 + (lq & 1) * 8 + lr;
                int col = kk + (lq >> 1) * 8;
                ldm4(ah[ma], aA + (uint32_t)(row * ASTRIDE + col) * 2);
            }
            #pragma unroll
            for (int np = 0; np < 2; np++) {
                // trans load: stored [k][n]; matrices (lq): k-tile = lq&1,
                // n-tile = lq>>1
                int row_k = kk + (lq & 1) * 8 + lr;
                int col_n = wn * 32 + np * 16 + (lq >> 1) * 8;
                uint32_t r4[4];
                ldm4t(r4, aB + (uint32_t)(row_k * BSTRIDE + col_n) * 2);
                bh[np * 2][0] = r4[0]; bh[np * 2][1] = r4[1];
                bh[np * 2 + 1][0] = r4[2]; bh[np * 2 + 1][1] = r4[3];
            }
            #pragma unroll
            for (int ma = 0; ma < 4; ma++)
                #pragma unroll
                for (int na = 0; na < 4; na++)
                    mma16816h(acc[ma][na], ah[ma], bh[na]);
        }
        __syncthreads();
        buf ^= 1;
    }

    // Epilogue: order-2 output, diag zero, x3 replication
    float* obase = out + (size_t)(v * 2 + 1) * OUT_G;
    #pragma unroll
    for (int ma = 0; ma < 4; ma++) {
        #pragma unroll
        for (int rr = 0; rr < 2; rr++) {
            int n = row0 + wm * 64 + ma * 16 + g + rr * 8;
            size_t orow = (size_t)(b * Nn + n) * (KTt * Nn);
            #pragma unroll
            for (int na = 0; na < 4; na++) {
                int col = col0 + wn * 32 + na * 8 + tig * 2;
                float v0 = acc[ma][na][rr * 2 + 0];
                float v1 = acc[ma][na][rr * 2 + 1];
                if (n == col)     v0 = 0.0f;
                if (n == col + 1) v1 = 0.0f;
                float2 o = make_float2(v0, v1);
                *(float2*)(obase + orow + col)          = o;
                *(float2*)(obase + orow + Nn + col)     = o;
                *(float2*)(obase + orow + 2 * Nn + col) = o;
            }
        }
    }
}

// ---------------------------------------------------------------------------
extern "C" void kernel_launch(void* const* d_in, const int* in_sizes, int n_in,
                              void* d_out, int out_size)
{
    const float* hist = (const float*)d_in[0];
    const float* embd = (const float*)d_in[1];
    const float* embu = (const float*)d_in[2];
    const float* tdf  = (const float*)d_in[3];
    const float* dwf  = (const float*)d_in[4];
    const float* m0   = (const float*)d_in[5];
    const float* m1   = (const float*)d_in[6];
    const float* W1   = (const float*)d_in[7];
    const float* b1   = (const float*)d_in[8];
    const float* gam  = (const float*)d_in[9];
    const float* bet  = (const float*)d_in[10];
    const float* mu   = (const float*)d_in[11];
    const float* var  = (const float*)d_in[12];
    const float* W2   = (const float*)d_in[13];
    const float* b2   = (const float*)d_in[14];
    const float* WQ   = (const float*)d_in[15];
    const float* WK   = (const float*)d_in[16];
    float* out = (float*)d_out;

    // One-time host-side resources (created on the un-captured correctness
    // call; no device memory involved).
    static cudaStream_t s1 = nullptr;
    static cudaEvent_t ev0 = nullptr, ev1 = nullptr;
    if (s1 == nullptr) {
        cudaStreamCreateWithFlags(&s1, cudaStreamNonBlocking);
        cudaEventCreateWithFlags(&ev0, cudaEventDisableTiming);
        cudaEventCreateWithFlags(&ev1, cudaEventDisableTiming);
        cudaFuncSetAttribute(qk_kernel,
                             cudaFuncAttributeMaxDynamicSharedMemorySize, QK_SMEM);
        cudaFuncSetAttribute(scores_mma_kernel,
                             cudaFuncAttributeMaxDynamicSharedMemorySize, SC_SMEM);
        cudaFuncSetAttribute(sq_mma_kernel,
                             cudaFuncAttributeMaxDynamicSharedMemorySize, SQ_SMEM);
    }

    feat_kernel<<<dim3(Nn, Bb), 128>>>(hist, embd, embu, tdf, dwf,
                                       W1, b1, gam, bet, mu, var, W2, b2);
    qk_kernel<<<dim3(Nn / 128, Bb), 256, QK_SMEM>>>(WQ, WK);

    // Fork: combos {2,3} on s1, combos {0,1} on the main stream.
    cudaEventRecord(ev0, 0);
    cudaStreamWaitEvent(s1, ev0, 0);

    scores_mma_kernel<<<dim3(16, 16, 2), 256, SC_SMEM, s1>>>(2);
    softmax_kernel<<<dim3(Nn, 2), 256, 0, s1>>>(m0, m1, out, 2);
    sq_mma_kernel<<<dim3(16, 16, 2), 256, SQ_SMEM, s1>>>(out, 2);

    scores_mma_kernel<<<dim3(16, 16, 2), 256, SC_SMEM>>>(0);
    softmax_kernel<<<dim3(Nn, 2), 256>>>(m0, m1, out, 0);
    sq_mma_kernel<<<dim3(16, 16, 2), 256, SQ_SMEM>>>(out, 0);

    // Join
    cudaEventRecord(ev1, s1);
    cudaStreamWaitEvent(0, ev1, 0);
}

// round 7
// speedup vs baseline: 4.3515x; 1.0260x over previous
#include <cuda_runtime.h>
#include <cuda_fp16.h>
#include <math.h>
#include <cstdint>

// Problem constants
#define Bb  2
#define Ll  12
#define Nn  2048
#define Hh  64
#define NDe 32
#define TEe 10
#define Ff  148
#define F2  116
#define KTt 3

static const size_t OUT_G = (size_t)Bb * Nn * KTt * Nn;

// Scratch (allocation-free rule: device globals)
__device__ float g_feat[(size_t)Bb * Nn * Ff];
__device__ __half g_Qh[(size_t)4 * Nn * Hh];   // 0.125*Q hi (fp16)
__device__ __half g_Ql[(size_t)4 * Nn * Hh];   // 0.125*Q lo
__device__ __half g_Kh[(size_t)4 * Nn * Hh];   // K hi
__device__ __half g_Kl[(size_t)4 * Nn * Hh];   // K lo
__device__ float g_S[(size_t)4 * Nn * Nn];
__device__ __half g_Ah[(size_t)4 * Nn * Nn];   // A (fp16), row-major [m][k]

// ===========================================================================
// Baseline-ISA helpers
// ===========================================================================
__device__ __forceinline__ void cpa16(uint32_t dst, const void* src) {
    asm volatile("cp.async.cg.shared.global [%0], [%1], 16;"
                 :: "r"(dst), "l"(src));
}
__device__ __forceinline__ void cpa_commit() {
    asm volatile("cp.async.commit_group;" ::: "memory");
}
template <int N> __device__ __forceinline__ void cpa_wait() {
    asm volatile("cp.async.wait_group %0;" :: "n"(N) : "memory");
}
__device__ __forceinline__ uint32_t s2u(const void* p) {
    uint32_t a;
    asm("{ .reg .u64 t; cvta.to.shared.u64 t, %1; cvt.u32.u64 %0, t; }"
        : "=r"(a) : "l"(p));
    return a;
}
__device__ __forceinline__ void mma16816h(float* d, const uint32_t* a,
                                          const uint32_t* b) {
    asm volatile(
        "mma.sync.aligned.m16n8k16.row.col.f32.f16.f16.f32 "
        "{%0,%1,%2,%3}, {%4,%5,%6,%7}, {%8,%9}, {%0,%1,%2,%3};"
        : "+f"(d[0]), "+f"(d[1]), "+f"(d[2]), "+f"(d[3])
        : "r"(a[0]), "r"(a[1]), "r"(a[2]), "r"(a[3]), "r"(b[0]), "r"(b[1]));
}
__device__ __forceinline__ void ldm4(uint32_t* r, uint32_t addr) {
    asm volatile("ldmatrix.sync.aligned.m8n8.x4.shared.b16 {%0,%1,%2,%3}, [%4];"
                 : "=r"(r[0]), "=r"(r[1]), "=r"(r[2]), "=r"(r[3]) : "r"(addr));
}
__device__ __forceinline__ void ldm4t(uint32_t* r, uint32_t addr) {
    asm volatile("ldmatrix.sync.aligned.m8n8.x4.trans.shared.b16 {%0,%1,%2,%3}, [%4];"
                 : "=r"(r[0]), "=r"(r[1]), "=r"(r[2]), "=r"(r[3]) : "r"(addr));
}

// ---------------------------------------------------------------------------
// Kernel 1: per-node feature prep (unchanged)
// ---------------------------------------------------------------------------
__global__ void __launch_bounds__(128) feat_kernel(
    const float* __restrict__ hist, const float* __restrict__ embd,
    const float* __restrict__ embu, const float* __restrict__ tdf,
    const float* __restrict__ dwf,
    const float* __restrict__ W1, const float* __restrict__ b1,
    const float* __restrict__ gamma, const float* __restrict__ beta,
    const float* __restrict__ mean, const float* __restrict__ var,
    const float* __restrict__ W2, const float* __restrict__ b2)
{
    int n = blockIdx.x, b = blockIdx.y, t = threadIdx.x;
    __shared__ float Xs[12];
    __shared__ float hs[128];
    __shared__ float fs[64];
    __shared__ float W1s[128 * 12];
    __shared__ float W2s[128 * 65];

    for (int i = t; i < 128 * 12; i += 128) W1s[i] = W1[i];
    for (int i = t; i < 64 * 128; i += 128) {
        int j = i >> 7, k = i & 127;
        W2s[k * 65 + j] = W2[i];
    }
    if (t < 12) Xs[t] = hist[(((size_t)b * Ll + t) * Nn + n) * 3];
    __syncthreads();

    {
        float acc = b1[t];
        #pragma unroll
        for (int l = 0; l < 12; l++) acc = fmaf(Xs[l], W1s[t * 12 + l], acc);
        acc = fmaxf(acc, 0.0f);
        acc = (acc - mean[t]) * (gamma[t] / sqrtf(var[t] + 1e-5f)) + beta[t];
        hs[t] = acc;
    }
    __syncthreads();

    if (t < 64) {
        float acc = b2[t];
        #pragma unroll 16
        for (int k = 0; k < 128; k++) acc = fmaf(hs[k], W2s[k * 65 + t], acc);
        fs[t] = acc;
    }
    __syncthreads();

    float* fr = g_feat + ((size_t)b * Nn + n) * Ff;
    size_t tbase = (((size_t)b * Ll + (Ll - 1)) * Nn + n) * TEe;
    for (int f = t; f < Ff; f += 128) {
        float val;
        if      (f < 64)  val = fs[f];
        else if (f < 74)  val = tdf[tbase + f - 64];
        else if (f < 84)  val = dwf[tbase + f - 74];
        else if (f < 116) val = embd[(size_t)n * NDe + (f - 84)];
        else              val = embu[(size_t)n * NDe + (f - 116)];
        fr[f] = val;
    }
}

// ---------------------------------------------------------------------------
// Kernel 2: Q/K projections -> fp16 hi/lo (Q pre-scaled by 1/sqrt(H))
// ---------------------------------------------------------------------------
#define QK_SMEM ((Ff * 128 + 2 * F2 * 64) * (int)sizeof(float))

__global__ void __launch_bounds__(256) qk_kernel(
    const float* __restrict__ WQ, const float* __restrict__ WK)
{
    extern __shared__ float sm[];
    float* Fs  = sm;
    float* WQt = Fs + Ff * 128;
    float* WKt = WQt + F2 * 64;

    int node0 = blockIdx.x * 128;
    int b = blockIdx.y;
    int t = threadIdx.x;

    for (int i = t; i < 128 * Ff; i += 256) {
        int node = i / Ff, f = i - node * Ff;
        Fs[f * 128 + node] = g_feat[((size_t)b * Nn + node0 + node) * Ff + f];
    }
    for (int i = t; i < 64 * F2; i += 256) {
        int j = i / F2, f = i - j * F2;
        WQt[f * 64 + j] = WQ[i];
        WKt[f * 64 + j] = WK[i];
    }
    __syncthreads();

    int v = t >> 7, sel = (t >> 6) & 1, j = t & 63;
    const float* Wt = sel ? WKt : WQt;
    __half* dh = (sel ? g_Kh : g_Qh) + (size_t)(v * 2 + b) * Nn * Hh;
    __half* dl = (sel ? g_Kl : g_Ql) + (size_t)(v * 2 + b) * Nn * Hh;
    float scale = sel ? 1.0f : 0.125f;
    int ebase = 84 + 32 * v;

    for (int nb = 0; nb < 128; nb += 8) {
        float acc[8] = {0, 0, 0, 0, 0, 0, 0, 0};
        for (int f = 0; f < 84; f++) {
            float w = Wt[f * 64 + j];
            #pragma unroll
            for (int u = 0; u < 8; u++)
                acc[u] = fmaf(Fs[f * 128 + nb + u], w, acc[u]);
        }
        #pragma unroll 8
        for (int e = 0; e < 32; e++) {
            float w = Wt[(84 + e) * 64 + j];
            #pragma unroll
            for (int u = 0; u < 8; u++)
                acc[u] = fmaf(Fs[(ebase + e) * 128 + nb + u], w, acc[u]);
        }
        #pragma unroll
        for (int u = 0; u < 8; u++) {
            float sv = acc[u] * scale;
            __half h = __float2half_rn(sv);
            float lo = sv - __half2float(h);
            size_t idx = (size_t)(node0 + nb + u) * Hh + j;
            dh[idx] = h;
            dl[idx] = __float2half_rn(lo);
        }
    }
}

// ---------------------------------------------------------------------------
// Kernel 3: scores = (0.125*Q) @ K^T via fp16 HMMA, 3-pass hi/lo (exact).
// ---------------------------------------------------------------------------
#define SCSTRIDE 72
#define SC_ARR (128 * SCSTRIDE * 2)
#define SC_SMEM (4 * SC_ARR)

__global__ void __launch_bounds__(256, 2) scores_mma_kernel(int c)
{
    extern __shared__ char dsm[];
    int row0 = blockIdx.y * 128, col0 = blockIdx.x * 128;
    int t = threadIdx.x, wid = t >> 5, lane = t & 31;
    int g = lane >> 2, tig = lane & 3;
    int wm = wid >> 2, wn = wid & 3;
    int lq = lane >> 3, lr = lane & 7;

    size_t qb = (size_t)c * Nn * Hh;
    uint32_t sb = s2u(dsm);
    uint32_t aQh = sb, aQl = sb + SC_ARR, aKh = sb + 2 * SC_ARR,
             aKl = sb + 3 * SC_ARR;

    #pragma unroll
    for (int j = 0; j < 16; j++) {
        int idx = j * 256 + t;
        int arr = idx >> 10;
        int rem = idx & 1023;
        int rr = rem >> 3, seg = rem & 7;
        const __half* base = (arr == 0) ? g_Qh : (arr == 1) ? g_Ql
                           : (arr == 2) ? g_Kh : g_Kl;
        int grow = ((arr < 2) ? row0 : col0) + rr;
        cpa16(sb + (uint32_t)arr * SC_ARR + rr * (SCSTRIDE * 2) + seg * 16,
              base + qb + (size_t)grow * Hh + seg * 8);
    }
    cpa_commit();
    cpa_wait<0>();
    __syncthreads();

    float acc[4][4][4] = {};
    #pragma unroll
    for (int ks = 0; ks < 4; ks++) {
        int kk = ks * 16;
        uint32_t qh[4][4], ql[4][4], kh[4][2], kl[4][2];
        #pragma unroll
        for (int ma = 0; ma < 4; ma++) {
            int row = wm * 64 + ma * 16 + (lq & 1) * 8 + lr;
            int col = kk + (lq >> 1) * 8;
            uint32_t off = (uint32_t)(row * SCSTRIDE + col) * 2;
            ldm4(qh[ma], aQh + off);
            ldm4(ql[ma], aQl + off);
        }
        #pragma unroll
        for (int np = 0; np < 2; np++) {
            int nrow = wn * 32 + np * 16 + (lq >> 1) * 8 + lr;
            int col = kk + (lq & 1) * 8;
            uint32_t off = (uint32_t)(nrow * SCSTRIDE + col) * 2;
            uint32_t r4[4];
            ldm4(r4, aKh + off);
            kh[np * 2][0] = r4[0]; kh[np * 2][1] = r4[1];
            kh[np * 2 + 1][0] = r4[2]; kh[np * 2 + 1][1] = r4[3];
            ldm4(r4, aKl + off);
            kl[np * 2][0] = r4[0]; kl[np * 2][1] = r4[1];
            kl[np * 2 + 1][0] = r4[2]; kl[np * 2 + 1][1] = r4[3];
        }
        #pragma unroll
        for (int ma = 0; ma < 4; ma++)
            #pragma unroll
            for (int na = 0; na < 4; na++) {
                mma16816h(acc[ma][na], qh[ma], kh[na]);
                mma16816h(acc[ma][na], qh[ma], kl[na]);
                mma16816h(acc[ma][na], ql[ma], kh[na]);
            }
    }

    float* S = g_S + (size_t)c * Nn * Nn;
    #pragma unroll
    for (int ma = 0; ma < 4; ma++)
        #pragma unroll
        for (int rr = 0; rr < 2; rr++) {
            int n = row0 + wm * 64 + ma * 16 + g + rr * 8;
            #pragma unroll
            for (int na = 0; na < 4; na++) {
                int col = col0 + wn * 32 + na * 8 + tig * 2;
                *(float2*)(S + (size_t)n * Nn + col) =
                    make_float2(acc[ma][na][rr * 2 + 0], acc[ma][na][rr * 2 + 1]);
            }
        }
}

// ---------------------------------------------------------------------------
// Kernel 4: fused masked softmax + normalize; emits order-1 output + fp16 A
// ---------------------------------------------------------------------------
__global__ void __launch_bounds__(256) softmax_kernel(
    const float* __restrict__ mask0, const float* __restrict__ mask1,
    float* __restrict__ out, int c)
{
    int n = blockIdx.x, v = c >> 1, b = c & 1;
    int t = threadIdx.x;
    const float* srow = g_S + ((size_t)c * Nn + n) * Nn;
    const float* mrow = (v ? mask1 : mask0) + (size_t)n * Nn;

    float s[8];
    float lmax = -3.4e38f;
    #pragma unroll
    for (int i = 0; i < 8; i++) {
        s[i] = srow[t + i * 256];
        lmax = fmaxf(lmax, s[i]);
    }

    __shared__ float red[8];
    #pragma unroll
    for (int o = 16; o; o >>= 1)
        lmax = fmaxf(lmax, __shfl_xor_sync(0xffffffffu, lmax, o));
    if ((t & 31) == 0) red[t >> 5] = lmax;
    __syncthreads();
    float rmax = red[0];
    #pragma unroll
    for (int w = 1; w < 8; w++) rmax = fmaxf(rmax, red[w]);
    __syncthreads();

    float wv[8], lsum = 0.0f;
    #pragma unroll
    for (int i = 0; i < 8; i++) {
        wv[i] = (mrow[t + i * 256] + 1e-7f) * expf(s[i] - rmax);
        lsum += wv[i];
    }
    #pragma unroll
    for (int o = 16; o; o >>= 1)
        lsum += __shfl_xor_sync(0xffffffffu, lsum, o);
    if ((t & 31) == 0) red[t >> 5] = lsum;
    __syncthreads();
    float tot = 0.0f;
    #pragma unroll
    for (int w = 0; w < 8; w++) tot += red[w];
    float inv = 1.0f / tot;

    size_t abase = ((size_t)c * Nn + n) * Nn;
    float* orow = out + (size_t)(v * 2) * OUT_G + (size_t)(b * Nn + n) * KTt * Nn;
    #pragma unroll
    for (int i = 0; i < 8; i++) {
        int m = t + i * 256;
        float val = wv[i] * inv;
        g_Ah[abase + m] = __float2half_rn(val);
        float ov = (m == n) ? 0.0f : val;
        orow[m] = ov;
        orow[Nn + m] = ov;
        orow[2 * Nn + m] = ov;
    }
}

// ---------------------------------------------------------------------------
// Kernel 5: C = A @ A via fp16 mma.sync, single pass, B via ldmatrix.trans.
// CTA 128x128, 8 warps of 64x32, K-chunk 64, double-buffered cp.async.
// ---------------------------------------------------------------------------
#define ASTRIDE 72                           // A tile: 128 x 64 halves (+8 pad)
#define BSTRIDE 136                          // B tile: 64 x 128 halves (+8 pad)
#define A_B (128 * ASTRIDE * 2)              // 18432 B
#define B_B (64 * BSTRIDE * 2)               // 17408 B
#define BUF_B (A_B + B_B)                    // 35840 B
#define SQ_SMEM (2 * BUF_B)                  // 71680 B

__global__ void __launch_bounds__(256, 2) sq_mma_kernel(float* __restrict__ out,
                                                        int c)
{
    extern __shared__ char dsm[];
    int v = c >> 1, b = c & 1;
    int row0 = blockIdx.y * 128, col0 = blockIdx.x * 128;
    int t = threadIdx.x, wid = t >> 5, lane = t & 31;
    int g = lane >> 2, tig = lane & 3;
    int wm = wid >> 2, wn = wid & 3;
    int lq = lane >> 3, lr = lane & 7;

    size_t cb = (size_t)c * Nn * Nn;
    const __half* Ahg = g_Ah + cb;

    uint32_t sbase = s2u(dsm);
    float acc[4][4][4] = {};

    auto load_stage = [&](int s, int kc) {
        uint32_t sb = sbase + (uint32_t)s * BUF_B;
        int k0 = kc * 64;
        #pragma unroll
        for (int j = 0; j < 4; j++) {        // A tile: 128 x 64 halves
            int idx = j * 256 + t;           // 0..1023
            int rr = idx >> 3, seg = idx & 7;
            cpa16(sb + rr * (ASTRIDE * 2) + seg * 16,
                  Ahg + (size_t)(row0 + rr) * Nn + k0 + seg * 8);
        }
        #pragma unroll
        for (int j = 0; j < 4; j++) {        // B tile: A[k0..k0+63][col0..+127]
            int idx = j * 256 + t;
            int rr = idx >> 4, seg = idx & 15;
            cpa16(sb + A_B + rr * (BSTRIDE * 2) + seg * 16,
                  Ahg + (size_t)(k0 + rr) * Nn + col0 + seg * 8);
        }
        cpa_commit();
    };

    load_stage(0, 0);

    int buf = 0;
    for (int kc = 0; kc < 32; kc++) {
        if (kc + 1 < 32) {
            load_stage(buf ^ 1, kc + 1);
            cpa_wait<1>();
        } else {
            cpa_wait<0>();
        }
        __syncthreads();

        uint32_t sb = sbase + (uint32_t)buf * BUF_B;
        uint32_t aA = sb, aB = sb + A_B;

        #pragma unroll
        for (int ks = 0; ks < 4; ks++) {
            int kk = ks * 16;
            uint32_t ah[4][4], bh[4][2];
            #pragma unroll
            for (int ma = 0; ma < 4; ma++) {
                int row = wm * 64 + ma * 16 + (lq & 1) * 8 + lr;
                int col = kk + (lq >> 1) * 8;
                ldm4(ah[ma], aA + (uint32_t)(row * ASTRIDE + col) * 2);
            }
            #pragma unroll
            for (int np = 0; np < 2; np++) {
                int row_k = kk + (lq & 1) * 8 + lr;
                int col_n = wn * 32 + np * 16 + (lq >> 1) * 8;
                uint32_t r4[4];
                ldm4t(r4, aB + (uint32_t)(row_k * BSTRIDE + col_n) * 2);
                bh[np * 2][0] = r4[0]; bh[np * 2][1] = r4[1];
                bh[np * 2 + 1][0] = r4[2]; bh[np * 2 + 1][1] = r4[3];
            }
            #pragma unroll
            for (int ma = 0; ma < 4; ma++)
                #pragma unroll
                for (int na = 0; na < 4; na++)
                    mma16816h(acc[ma][na], ah[ma], bh[na]);
        }
        __syncthreads();
        buf ^= 1;
    }

    // Epilogue: order-2 output, diag zero, x3 replication
    float* obase = out + (size_t)(v * 2 + 1) * OUT_G;
    #pragma unroll
    for (int ma = 0; ma < 4; ma++) {
        #pragma unroll
        for (int rr = 0; rr < 2; rr++) {
            int n = row0 + wm * 64 + ma * 16 + g + rr * 8;
            size_t orow = (size_t)(b * Nn + n) * (KTt * Nn);
            #pragma unroll
            for (int na = 0; na < 4; na++) {
                int col = col0 + wn * 32 + na * 8 + tig * 2;
                float v0 = acc[ma][na][rr * 2 + 0];
                float v1 = acc[ma][na][rr * 2 + 1];
                if (n == col)     v0 = 0.0f;
                if (n == col + 1) v1 = 0.0f;
                float2 o = make_float2(v0, v1);
                *(float2*)(obase + orow + col)          = o;
                *(float2*)(obase + orow + Nn + col)     = o;
                *(float2*)(obase + orow + 2 * Nn + col) = o;
            }
        }
    }
}

// ---------------------------------------------------------------------------
extern "C" void kernel_launch(void* const* d_in, const int* in_sizes, int n_in,
                              void* d_out, int out_size)
{
    const float* hist = (const float*)d_in[0];
    const float* embd = (const float*)d_in[1];
    const float* embu = (const float*)d_in[2];
    const float* tdf  = (const float*)d_in[3];
    const float* dwf  = (const float*)d_in[4];
    const float* m0   = (const float*)d_in[5];
    const float* m1   = (const float*)d_in[6];
    const float* W1   = (const float*)d_in[7];
    const float* b1   = (const float*)d_in[8];
    const float* gam  = (const float*)d_in[9];
    const float* bet  = (const float*)d_in[10];
    const float* mu   = (const float*)d_in[11];
    const float* var  = (const float*)d_in[12];
    const float* W2   = (const float*)d_in[13];
    const float* b2   = (const float*)d_in[14];
    const float* WQ   = (const float*)d_in[15];
    const float* WK   = (const float*)d_in[16];
    float* out = (float*)d_out;

    // One-time host-side resources (created on the un-captured correctness run)
    static cudaStream_t st[3] = {nullptr, nullptr, nullptr};
    static cudaEvent_t evf = nullptr, evj[3] = {nullptr, nullptr, nullptr};
    if (st[0] == nullptr) {
        for (int i = 0; i < 3; i++) {
            cudaStreamCreateWithFlags(&st[i], cudaStreamNonBlocking);
            cudaEventCreateWithFlags(&evj[i], cudaEventDisableTiming);
        }
        cudaEventCreateWithFlags(&evf, cudaEventDisableTiming);
        cudaFuncSetAttribute(qk_kernel,
                             cudaFuncAttributeMaxDynamicSharedMemorySize, QK_SMEM);
        cudaFuncSetAttribute(scores_mma_kernel,
                             cudaFuncAttributeMaxDynamicSharedMemorySize, SC_SMEM);
        cudaFuncSetAttribute(sq_mma_kernel,
                             cudaFuncAttributeMaxDynamicSharedMemorySize, SQ_SMEM);
    }

    feat_kernel<<<dim3(Nn, Bb), 128>>>(hist, embd, embu, tdf, dwf,
                                       W1, b1, gam, bet, mu, var, W2, b2);
    qk_kernel<<<dim3(Nn / 128, Bb), 256, QK_SMEM>>>(WQ, WK);

    // Fork: combo 0 on legacy stream, combos 1..3 on st[0..2]
    cudaEventRecord(evf, 0);
    for (int i = 0; i < 3; i++) cudaStreamWaitEvent(st[i], evf, 0);

    scores_mma_kernel<<<dim3(16, 16, 1), 256, SC_SMEM>>>(0);
    for (int i = 0; i < 3; i++)
        scores_mma_kernel<<<dim3(16, 16, 1), 256, SC_SMEM, st[i]>>>(i + 1);

    softmax_kernel<<<dim3(Nn, 1), 256>>>(m0, m1, out, 0);
    for (int i = 0; i < 3; i++)
        softmax_kernel<<<dim3(Nn, 1), 256, 0, st[i]>>>(m0, m1, out, i + 1);

    sq_mma_kernel<<<dim3(16, 16, 1), 256, SQ_SMEM>>>(out, 0);
    for (int i = 0; i < 3; i++)
        sq_mma_kernel<<<dim3(16, 16, 1), 256, SQ_SMEM, st[i]>>>(out, i + 1);

    // Join
    for (int i = 0; i < 3; i++) {
        cudaEventRecord(evj[i], st[i]);
        cudaStreamWaitEvent(0, evj[i], 0);
    }
}

// round 9
// speedup vs baseline: 4.4216x; 1.0161x over previous
#include <cuda_runtime.h>
#include <cuda_fp16.h>
#include <math.h>
#include <cstdint>

// Problem constants
#define Bb  2
#define Ll  12
#define Nn  2048
#define Hh  64
#define NDe 32
#define TEe 10
#define Ff  148
#define F2  116
#define KTt 3

static const size_t OUT_G = (size_t)Bb * Nn * KTt * Nn;

// Scratch (allocation-free rule: device globals)
__device__ float g_feat[(size_t)Bb * Nn * Ff];
__device__ __half g_Qh[(size_t)4 * Nn * Hh];   // 0.125*Q hi (fp16)
__device__ __half g_Ql[(size_t)4 * Nn * Hh];   // 0.125*Q lo
__device__ __half g_Kh[(size_t)4 * Nn * Hh];   // K hi
__device__ __half g_Kl[(size_t)4 * Nn * Hh];   // K lo
__device__ float g_S[(size_t)4 * Nn * Nn];
__device__ __half g_Ah[(size_t)4 * Nn * Nn];   // A (fp16), row-major [m][k]

// ===========================================================================
// Baseline-ISA helpers
// ===========================================================================
__device__ __forceinline__ void cpa16(uint32_t dst, const void* src) {
    asm volatile("cp.async.cg.shared.global [%0], [%1], 16;"
                 :: "r"(dst), "l"(src));
}
__device__ __forceinline__ void cpa_commit() {
    asm volatile("cp.async.commit_group;" ::: "memory");
}
template <int N> __device__ __forceinline__ void cpa_wait() {
    asm volatile("cp.async.wait_group %0;" :: "n"(N) : "memory");
}
__device__ __forceinline__ uint32_t s2u(const void* p) {
    uint32_t a;
    asm("{ .reg .u64 t; cvta.to.shared.u64 t, %1; cvt.u32.u64 %0, t; }"
        : "=r"(a) : "l"(p));
    return a;
}
__device__ __forceinline__ void mma16816h(float* d, const uint32_t* a,
                                          const uint32_t* b) {
    asm volatile(
        "mma.sync.aligned.m16n8k16.row.col.f32.f16.f16.f32 "
        "{%0,%1,%2,%3}, {%4,%5,%6,%7}, {%8,%9}, {%0,%1,%2,%3};"
        : "+f"(d[0]), "+f"(d[1]), "+f"(d[2]), "+f"(d[3])
        : "r"(a[0]), "r"(a[1]), "r"(a[2]), "r"(a[3]), "r"(b[0]), "r"(b[1]));
}
__device__ __forceinline__ void ldm4(uint32_t* r, uint32_t addr) {
    asm volatile("ldmatrix.sync.aligned.m8n8.x4.shared.b16 {%0,%1,%2,%3}, [%4];"
                 : "=r"(r[0]), "=r"(r[1]), "=r"(r[2]), "=r"(r[3]) : "r"(addr));
}
__device__ __forceinline__ void ldm4t(uint32_t* r, uint32_t addr) {
    asm volatile("ldmatrix.sync.aligned.m8n8.x4.trans.shared.b16 {%0,%1,%2,%3}, [%4];"
                 : "=r"(r[0]), "=r"(r[1]), "=r"(r[2]), "=r"(r[3]) : "r"(addr));
}

// ---------------------------------------------------------------------------
// Kernel 1: per-node feature prep (unchanged)
// ---------------------------------------------------------------------------
__global__ void __launch_bounds__(128) feat_kernel(
    const float* __restrict__ hist, const float* __restrict__ embd,
    const float* __restrict__ embu, const float* __restrict__ tdf,
    const float* __restrict__ dwf,
    const float* __restrict__ W1, const float* __restrict__ b1,
    const float* __restrict__ gamma, const float* __restrict__ beta,
    const float* __restrict__ mean, const float* __restrict__ var,
    const float* __restrict__ W2, const float* __restrict__ b2)
{
    int n = blockIdx.x, b = blockIdx.y, t = threadIdx.x;
    __shared__ float Xs[12];
    __shared__ float hs[128];
    __shared__ float fs[64];
    __shared__ float W1s[128 * 12];
    __shared__ float W2s[128 * 65];

    for (int i = t; i < 128 * 12; i += 128) W1s[i] = W1[i];
    for (int i = t; i < 64 * 128; i += 128) {
        int j = i >> 7, k = i & 127;
        W2s[k * 65 + j] = W2[i];
    }
    if (t < 12) Xs[t] = hist[(((size_t)b * Ll + t) * Nn + n) * 3];
    __syncthreads();

    {
        float acc = b1[t];
        #pragma unroll
        for (int l = 0; l < 12; l++) acc = fmaf(Xs[l], W1s[t * 12 + l], acc);
        acc = fmaxf(acc, 0.0f);
        acc = (acc - mean[t]) * (gamma[t] / sqrtf(var[t] + 1e-5f)) + beta[t];
        hs[t] = acc;
    }
    __syncthreads();

    if (t < 64) {
        float acc = b2[t];
        #pragma unroll 16
        for (int k = 0; k < 128; k++) acc = fmaf(hs[k], W2s[k * 65 + t], acc);
        fs[t] = acc;
    }
    __syncthreads();

    float* fr = g_feat + ((size_t)b * Nn + n) * Ff;
    size_t tbase = (((size_t)b * Ll + (Ll - 1)) * Nn + n) * TEe;
    for (int f = t; f < Ff; f += 128) {
        float val;
        if      (f < 64)  val = fs[f];
        else if (f < 74)  val = tdf[tbase + f - 64];
        else if (f < 84)  val = dwf[tbase + f - 74];
        else if (f < 116) val = embd[(size_t)n * NDe + (f - 84)];
        else              val = embu[(size_t)n * NDe + (f - 116)];
        fr[f] = val;
    }
}

// ---------------------------------------------------------------------------
// Kernel 2: Q/K projections -> fp16 hi/lo (Q pre-scaled by 1/sqrt(H))
// ---------------------------------------------------------------------------
#define QK_SMEM ((Ff * 128 + 2 * F2 * 64) * (int)sizeof(float))

__global__ void __launch_bounds__(256) qk_kernel(
    const float* __restrict__ WQ, const float* __restrict__ WK)
{
    extern __shared__ float sm[];
    float* Fs  = sm;
    float* WQt = Fs + Ff * 128;
    float* WKt = WQt + F2 * 64;

    int node0 = blockIdx.x * 128;
    int b = blockIdx.y;
    int t = threadIdx.x;

    for (int i = t; i < 128 * Ff; i += 256) {
        int node = i / Ff, f = i - node * Ff;
        Fs[f * 128 + node] = g_feat[((size_t)b * Nn + node0 + node) * Ff + f];
    }
    for (int i = t; i < 64 * F2; i += 256) {
        int j = i / F2, f = i - j * F2;
        WQt[f * 64 + j] = WQ[i];
        WKt[f * 64 + j] = WK[i];
    }
    __syncthreads();

    int v = t >> 7, sel = (t >> 6) & 1, j = t & 63;
    const float* Wt = sel ? WKt : WQt;
    __half* dh = (sel ? g_Kh : g_Qh) + (size_t)(v * 2 + b) * Nn * Hh;
    __half* dl = (sel ? g_Kl : g_Ql) + (size_t)(v * 2 + b) * Nn * Hh;
    float scale = sel ? 1.0f : 0.125f;
    int ebase = 84 + 32 * v;

    for (int nb = 0; nb < 128; nb += 8) {
        float acc[8] = {0, 0, 0, 0, 0, 0, 0, 0};
        for (int f = 0; f < 84; f++) {
            float w = Wt[f * 64 + j];
            #pragma unroll
            for (int u = 0; u < 8; u++)
                acc[u] = fmaf(Fs[f * 128 + nb + u], w, acc[u]);
        }
        #pragma unroll 8
        for (int e = 0; e < 32; e++) {
            float w = Wt[(84 + e) * 64 + j];
            #pragma unroll
            for (int u = 0; u < 8; u++)
                acc[u] = fmaf(Fs[(ebase + e) * 128 + nb + u], w, acc[u]);
        }
        #pragma unroll
        for (int u = 0; u < 8; u++) {
            float sv = acc[u] * scale;
            __half h = __float2half_rn(sv);
            float lo = sv - __half2float(h);
            size_t idx = (size_t)(node0 + nb + u) * Hh + j;
            dh[idx] = h;
            dl[idx] = __float2half_rn(lo);
        }
    }
}

// ---------------------------------------------------------------------------
// Kernel 3: scores = (0.125*Q) @ K^T via fp16 HMMA, 3-pass hi/lo (exact).
// ---------------------------------------------------------------------------
#define SCSTRIDE 72
#define SC_ARR (128 * SCSTRIDE * 2)
#define SC_SMEM (4 * SC_ARR)

__global__ void __launch_bounds__(256, 2) scores_mma_kernel(int c)
{
    extern __shared__ char dsm[];
    int row0 = blockIdx.y * 128, col0 = blockIdx.x * 128;
    int t = threadIdx.x, wid = t >> 5, lane = t & 31;
    int g = lane >> 2, tig = lane & 3;
    int wm = wid >> 2, wn = wid & 3;
    int lq = lane >> 3, lr = lane & 7;

    size_t qb = (size_t)c * Nn * Hh;
    uint32_t sb = s2u(dsm);
    uint32_t aQh = sb, aQl = sb + SC_ARR, aKh = sb + 2 * SC_ARR,
             aKl = sb + 3 * SC_ARR;

    #pragma unroll
    for (int j = 0; j < 16; j++) {
        int idx = j * 256 + t;
        int arr = idx >> 10;
        int rem = idx & 1023;
        int rr = rem >> 3, seg = rem & 7;
        const __half* base = (arr == 0) ? g_Qh : (arr == 1) ? g_Ql
                           : (arr == 2) ? g_Kh : g_Kl;
        int grow = ((arr < 2) ? row0 : col0) + rr;
        cpa16(sb + (uint32_t)arr * SC_ARR + rr * (SCSTRIDE * 2) + seg * 16,
              base + qb + (size_t)grow * Hh + seg * 8);
    }
    cpa_commit();
    cpa_wait<0>();
    __syncthreads();

    float acc[4][4][4] = {};
    #pragma unroll
    for (int ks = 0; ks < 4; ks++) {
        int kk = ks * 16;
        uint32_t qh[4][4], ql[4][4], kh[4][2], kl[4][2];
        #pragma unroll
        for (int ma = 0; ma < 4; ma++) {
            int row = wm * 64 + ma * 16 + (lq & 1) * 8 + lr;
            int col = kk + (lq >> 1) * 8;
            uint32_t off = (uint32_t)(row * SCSTRIDE + col) * 2;
            ldm4(qh[ma], aQh + off);
            ldm4(ql[ma], aQl + off);
        }
        #pragma unroll
        for (int np = 0; np < 2; np++) {
            int nrow = wn * 32 + np * 16 + (lq >> 1) * 8 + lr;
            int col = kk + (lq & 1) * 8;
            uint32_t off = (uint32_t)(nrow * SCSTRIDE + col) * 2;
            uint32_t r4[4];
            ldm4(r4, aKh + off);
            kh[np * 2][0] = r4[0]; kh[np * 2][1] = r4[1];
            kh[np * 2 + 1][0] = r4[2]; kh[np * 2 + 1][1] = r4[3];
            ldm4(r4, aKl + off);
            kl[np * 2][0] = r4[0]; kl[np * 2][1] = r4[1];
            kl[np * 2 + 1][0] = r4[2]; kl[np * 2 + 1][1] = r4[3];
        }
        #pragma unroll
        for (int ma = 0; ma < 4; ma++)
            #pragma unroll
            for (int na = 0; na < 4; na++) {
                mma16816h(acc[ma][na], qh[ma], kh[na]);
                mma16816h(acc[ma][na], qh[ma], kl[na]);
                mma16816h(acc[ma][na], ql[ma], kh[na]);
            }
    }

    float* S = g_S + (size_t)c * Nn * Nn;
    #pragma unroll
    for (int ma = 0; ma < 4; ma++)
        #pragma unroll
        for (int rr = 0; rr < 2; rr++) {
            int n = row0 + wm * 64 + ma * 16 + g + rr * 8;
            #pragma unroll
            for (int na = 0; na < 4; na++) {
                int col = col0 + wn * 32 + na * 8 + tig * 2;
                *(float2*)(S + (size_t)n * Nn + col) =
                    make_float2(acc[ma][na][rr * 2 + 0], acc[ma][na][rr * 2 + 1]);
            }
        }
}

// ---------------------------------------------------------------------------
// Kernel 4: fused masked softmax + normalize; emits order-1 output + fp16 A
// ---------------------------------------------------------------------------
__global__ void __launch_bounds__(256) softmax_kernel(
    const float* __restrict__ mask0, const float* __restrict__ mask1,
    float* __restrict__ out, int c)
{
    int n = blockIdx.x, v = c >> 1, b = c & 1;
    int t = threadIdx.x;
    const float* srow = g_S + ((size_t)c * Nn + n) * Nn;
    const float* mrow = (v ? mask1 : mask0) + (size_t)n * Nn;

    float s[8];
    float lmax = -3.4e38f;
    #pragma unroll
    for (int i = 0; i < 8; i++) {
        s[i] = srow[t + i * 256];
        lmax = fmaxf(lmax, s[i]);
    }

    __shared__ float red[8];
    #pragma unroll
    for (int o = 16; o; o >>= 1)
        lmax = fmaxf(lmax, __shfl_xor_sync(0xffffffffu, lmax, o));
    if ((t & 31) == 0) red[t >> 5] = lmax;
    __syncthreads();
    float rmax = red[0];
    #pragma unroll
    for (int w = 1; w < 8; w++) rmax = fmaxf(rmax, red[w]);
    __syncthreads();

    float wv[8], lsum = 0.0f;
    #pragma unroll
    for (int i = 0; i < 8; i++) {
        wv[i] = (mrow[t + i * 256] + 1e-7f) * expf(s[i] - rmax);
        lsum += wv[i];
    }
    #pragma unroll
    for (int o = 16; o; o >>= 1)
        lsum += __shfl_xor_sync(0xffffffffu, lsum, o);
    if ((t & 31) == 0) red[t >> 5] = lsum;
    __syncthreads();
    float tot = 0.0f;
    #pragma unroll
    for (int w = 0; w < 8; w++) tot += red[w];
    float inv = 1.0f / tot;

    size_t abase = ((size_t)c * Nn + n) * Nn;
    float* orow = out + (size_t)(v * 2) * OUT_G + (size_t)(b * Nn + n) * KTt * Nn;
    #pragma unroll
    for (int i = 0; i < 8; i++) {
        int m = t + i * 256;
        float val = wv[i] * inv;
        g_Ah[abase + m] = __float2half_rn(val);
        float ov = (m == n) ? 0.0f : val;
        orow[m] = ov;
        orow[Nn + m] = ov;
        orow[2 * Nn + m] = ov;
    }
}

// ---------------------------------------------------------------------------
// Kernel 5: C = A @ A via fp16 mma.sync, single pass, B via ldmatrix.trans.
// CTA 128x128, 4 warps of 64x64 (higher fragment reuse: 128 B/MMA vs 192),
// K-chunk 64, double-buffered cp.async. Epilogue: diag zero, x3 replicate.
// ---------------------------------------------------------------------------
#define ASTRIDE 72                           // A tile: 128 x 64 halves (+8 pad)
#define BSTRIDE 136                          // B tile: 64 x 128 halves (+8 pad)
#define A_B (128 * ASTRIDE * 2)              // 18432 B
#define B_B (64 * BSTRIDE * 2)               // 17408 B
#define BUF_B (A_B + B_B)                    // 35840 B
#define SQ_SMEM (2 * BUF_B)                  // 71680 B

__global__ void __launch_bounds__(128, 2) sq_mma_kernel(float* __restrict__ out,
                                                        int c)
{
    extern __shared__ char dsm[];
    int v = c >> 1, b = c & 1;
    int row0 = blockIdx.y * 128, col0 = blockIdx.x * 128;
    int t = threadIdx.x, wid = t >> 5, lane = t & 31;
    int g = lane >> 2, tig = lane & 3;
    int wm = wid >> 1, wn = wid & 1;         // warp tile: 64x64
    int lq = lane >> 3, lr = lane & 7;

    size_t cb = (size_t)c * Nn * Nn;
    const __half* Ahg = g_Ah + cb;

    uint32_t sbase = s2u(dsm);
    float acc[4][8][4] = {};

    auto load_stage = [&](int s, int kc) {
        uint32_t sb = sbase + (uint32_t)s * BUF_B;
        int k0 = kc * 64;
        #pragma unroll
        for (int j = 0; j < 8; j++) {        // A tile: 128 x 64 halves
            int idx = j * 128 + t;           // 0..1023
            int rr = idx >> 3, seg = idx & 7;
            cpa16(sb + rr * (ASTRIDE * 2) + seg * 16,
                  Ahg + (size_t)(row0 + rr) * Nn + k0 + seg * 8);
        }
        #pragma unroll
        for (int j = 0; j < 8; j++) {        // B tile: A[k0..k0+63][col0..+127]
            int idx = j * 128 + t;
            int rr = idx >> 4, seg = idx & 15;
            cpa16(sb + A_B + rr * (BSTRIDE * 2) + seg * 16,
                  Ahg + (size_t)(k0 + rr) * Nn + col0 + seg * 8);
        }
        cpa_commit();
    };

    load_stage(0, 0);

    int buf = 0;
    for (int kc = 0; kc < 32; kc++) {
        if (kc + 1 < 32) {
            load_stage(buf ^ 1, kc + 1);
            cpa_wait<1>();
        } else {
            cpa_wait<0>();
        }
        __syncthreads();

        uint32_t sb = sbase + (uint32_t)buf * BUF_B;
        uint32_t aA = sb, aB = sb + A_B;

        #pragma unroll
        for (int ks = 0; ks < 4; ks++) {
            int kk = ks * 16;
            uint32_t ah[4][4], bh[8][2];
            #pragma unroll
            for (int ma = 0; ma < 4; ma++) {
                int row = wm * 64 + ma * 16 + (lq & 1) * 8 + lr;
                int col = kk + (lq >> 1) * 8;
                ldm4(ah[ma], aA + (uint32_t)(row * ASTRIDE + col) * 2);
            }
            #pragma unroll
            for (int np = 0; np < 4; np++) {
                int row_k = kk + (lq & 1) * 8 + lr;
                int col_n = wn * 64 + np * 16 + (lq >> 1) * 8;
                uint32_t r4[4];
                ldm4t(r4, aB + (uint32_t)(row_k * BSTRIDE + col_n) * 2);
                bh[np * 2][0] = r4[0]; bh[np * 2][1] = r4[1];
                bh[np * 2 + 1][0] = r4[2]; bh[np * 2 + 1][1] = r4[3];
            }
            #pragma unroll
            for (int ma = 0; ma < 4; ma++)
                #pragma unroll
                for (int na = 0; na < 8; na++)
                    mma16816h(acc[ma][na], ah[ma], bh[na]);
        }
        __syncthreads();
        buf ^= 1;
    }

    // Epilogue: order-2 output, diag zero, x3 replication
    float* obase = out + (size_t)(v * 2 + 1) * OUT_G;
    #pragma unroll
    for (int ma = 0; ma < 4; ma++) {
        #pragma unroll
        for (int rr = 0; rr < 2; rr++) {
            int n = row0 + wm * 64 + ma * 16 + g + rr * 8;
            size_t orow = (size_t)(b * Nn + n) * (KTt * Nn);
            #pragma unroll
            for (int na = 0; na < 8; na++) {
                int col = col0 + wn * 64 + na * 8 + tig * 2;
                float v0 = acc[ma][na][rr * 2 + 0];
                float v1 = acc[ma][na][rr * 2 + 1];
                if (n == col)     v0 = 0.0f;
                if (n == col + 1) v1 = 0.0f;
                float2 o = make_float2(v0, v1);
                *(float2*)(obase + orow + col)          = o;
                *(float2*)(obase + orow + Nn + col)     = o;
                *(float2*)(obase + orow + 2 * Nn + col) = o;
            }
        }
    }
}

// ---------------------------------------------------------------------------
extern "C" void kernel_launch(void* const* d_in, const int* in_sizes, int n_in,
                              void* d_out, int out_size)
{
    const float* hist = (const float*)d_in[0];
    const float* embd = (const float*)d_in[1];
    const float* embu = (const float*)d_in[2];
    const float* tdf  = (const float*)d_in[3];
    const float* dwf  = (const float*)d_in[4];
    const float* m0   = (const float*)d_in[5];
    const float* m1   = (const float*)d_in[6];
    const float* W1   = (const float*)d_in[7];
    const float* b1   = (const float*)d_in[8];
    const float* gam  = (const float*)d_in[9];
    const float* bet  = (const float*)d_in[10];
    const float* mu   = (const float*)d_in[11];
    const float* var  = (const float*)d_in[12];
    const float* W2   = (const float*)d_in[13];
    const float* b2   = (const float*)d_in[14];
    const float* WQ   = (const float*)d_in[15];
    const float* WK   = (const float*)d_in[16];
    float* out = (float*)d_out;

    // One-time host-side resources (created on the un-captured correctness run)
    static cudaStream_t st[3] = {nullptr, nullptr, nullptr};
    static cudaEvent_t evf = nullptr, evj[3] = {nullptr, nullptr, nullptr};
    if (st[0] == nullptr) {
        for (int i = 0; i < 3; i++) {
            cudaStreamCreateWithFlags(&st[i], cudaStreamNonBlocking);
            cudaEventCreateWithFlags(&evj[i], cudaEventDisableTiming);
        }
        cudaEventCreateWithFlags(&evf, cudaEventDisableTiming);
        cudaFuncSetAttribute(qk_kernel,
                             cudaFuncAttributeMaxDynamicSharedMemorySize, QK_SMEM);
        cudaFuncSetAttribute(scores_mma_kernel,
                             cudaFuncAttributeMaxDynamicSharedMemorySize, SC_SMEM);
        cudaFuncSetAttribute(sq_mma_kernel,
                             cudaFuncAttributeMaxDynamicSharedMemorySize, SQ_SMEM);
    }

    feat_kernel<<<dim3(Nn, Bb), 128>>>(hist, embd, embu, tdf, dwf,
                                       W1, b1, gam, bet, mu, var, W2, b2);
    qk_kernel<<<dim3(Nn / 128, Bb), 256, QK_SMEM>>>(WQ, WK);

    // Fork: combo 0 on legacy stream, combos 1..3 on st[0..2]  (round-7
    // topology — passed cleanly twice; no cross-stream stagger edges)
    cudaEventRecord(evf, 0);
    for (int i = 0; i < 3; i++) cudaStreamWaitEvent(st[i], evf, 0);

    scores_mma_kernel<<<dim3(16, 16, 1), 256, SC_SMEM>>>(0);
    for (int i = 0; i < 3; i++)
        scores_mma_kernel<<<dim3(16, 16, 1), 256, SC_SMEM, st[i]>>>(i + 1);

    softmax_kernel<<<dim3(Nn, 1), 256>>>(m0, m1, out, 0);
    for (int i = 0; i < 3; i++)
        softmax_kernel<<<dim3(Nn, 1), 256, 0, st[i]>>>(m0, m1, out, i + 1);

    sq_mma_kernel<<<dim3(16, 16, 1), 128, SQ_SMEM>>>(out, 0);
    for (int i = 0; i < 3; i++)
        sq_mma_kernel<<<dim3(16, 16, 1), 128, SQ_SMEM, st[i]>>>(out, i + 1);

    // Join
    for (int i = 0; i < 3; i++) {
        cudaEventRecord(evj[i], st[i]);
        cudaStreamWaitEvent(0, evj[i], 0);
    }
}

// round 11
// speedup vs baseline: 4.7416x; 1.0724x over previous
#include <cuda_runtime.h>
#include <cuda_fp16.h>
#include <math.h>
#include <cstdint>

// Problem constants
#define Bb  2
#define Ll  12
#define Nn  2048
#define Hh  64
#define NDe 32
#define TEe 10
#define Ff  148
#define F2  116
#define KTt 3

static const size_t OUT_G = (size_t)Bb * Nn * KTt * Nn;

// Scratch (allocation-free rule: device globals)
__device__ float g_feat[(size_t)Bb * Nn * Ff];
__device__ __half g_Qh[(size_t)4 * Nn * Hh];   // 0.125*Q hi (fp16)
__device__ __half g_Ql[(size_t)4 * Nn * Hh];   // 0.125*Q lo
__device__ __half g_Kh[(size_t)4 * Nn * Hh];   // K hi
__device__ __half g_Kl[(size_t)4 * Nn * Hh];   // K lo
__device__ float g_S[(size_t)4 * Nn * Nn];
__device__ __half g_Ah[(size_t)4 * Nn * Nn];   // A (fp16), row-major [m][k]

// ===========================================================================
// Baseline-ISA helpers
// ===========================================================================
__device__ __forceinline__ void cpa16(uint32_t dst, const void* src) {
    asm volatile("cp.async.cg.shared.global [%0], [%1], 16;"
                 :: "r"(dst), "l"(src));
}
__device__ __forceinline__ void cpa_commit() {
    asm volatile("cp.async.commit_group;" ::: "memory");
}
template <int N> __device__ __forceinline__ void cpa_wait() {
    asm volatile("cp.async.wait_group %0;" :: "n"(N) : "memory");
}
__device__ __forceinline__ uint32_t s2u(const void* p) {
    uint32_t a;
    asm("{ .reg .u64 t; cvta.to.shared.u64 t, %1; cvt.u32.u64 %0, t; }"
        : "=r"(a) : "l"(p));
    return a;
}
__device__ __forceinline__ void mma16816h(float* d, const uint32_t* a,
                                          const uint32_t* b) {
    asm volatile(
        "mma.sync.aligned.m16n8k16.row.col.f32.f16.f16.f32 "
        "{%0,%1,%2,%3}, {%4,%5,%6,%7}, {%8,%9}, {%0,%1,%2,%3};"
        : "+f"(d[0]), "+f"(d[1]), "+f"(d[2]), "+f"(d[3])
        : "r"(a[0]), "r"(a[1]), "r"(a[2]), "r"(a[3]), "r"(b[0]), "r"(b[1]));
}
__device__ __forceinline__ void ldm4(uint32_t* r, uint32_t addr) {
    asm volatile("ldmatrix.sync.aligned.m8n8.x4.shared.b16 {%0,%1,%2,%3}, [%4];"
                 : "=r"(r[0]), "=r"(r[1]), "=r"(r[2]), "=r"(r[3]) : "r"(addr));
}
__device__ __forceinline__ void ldm4t(uint32_t* r, uint32_t addr) {
    asm volatile("ldmatrix.sync.aligned.m8n8.x4.trans.shared.b16 {%0,%1,%2,%3}, [%4];"
                 : "=r"(r[0]), "=r"(r[1]), "=r"(r[2]), "=r"(r[3]) : "r"(addr));
}

// ---------------------------------------------------------------------------
// Kernel 1: per-node feature prep. 8 nodes per CTA (weight staging amortized).
// ---------------------------------------------------------------------------
__global__ void __launch_bounds__(128) feat_kernel(
    const float* __restrict__ hist, const float* __restrict__ embd,
    const float* __restrict__ embu, const float* __restrict__ tdf,
    const float* __restrict__ dwf,
    const float* __restrict__ W1, const float* __restrict__ b1,
    const float* __restrict__ gamma, const float* __restrict__ beta,
    const float* __restrict__ mean, const float* __restrict__ var,
    const float* __restrict__ W2, const float* __restrict__ b2)
{
    int n0 = blockIdx.x * 8, b = blockIdx.y, t = threadIdx.x;
    __shared__ float Xs[8][12];
    __shared__ float hs[8][128];
    __shared__ float fs[8][64];
    __shared__ float W1s[128 * 12];
    __shared__ float W2s[128 * 65];

    for (int i = t; i < 128 * 12; i += 128) W1s[i] = W1[i];
    for (int i = t; i < 64 * 128; i += 128) {
        int j = i >> 7, k = i & 127;
        W2s[k * 65 + j] = W2[i];
    }
    if (t < 96) {
        int nn = t / 12, l = t - nn * 12;
        Xs[nn][l] = hist[(((size_t)b * Ll + l) * Nn + n0 + nn) * 3];
    }
    __syncthreads();

    {
        float bnb = beta[t], bnm = mean[t];
        float bns = gamma[t] / sqrtf(var[t] + 1e-5f);
        float bias = b1[t];
        #pragma unroll
        for (int nn = 0; nn < 8; nn++) {
            float acc = bias;
            #pragma unroll
            for (int l = 0; l < 12; l++)
                acc = fmaf(Xs[nn][l], W1s[t * 12 + l], acc);
            acc = fmaxf(acc, 0.0f);
            hs[nn][t] = (acc - bnm) * bns + bnb;
        }
    }
    __syncthreads();

    {
        int j = t & 63;
        float bias = b2[j];
        for (int nn = t >> 6; nn < 8; nn += 2) {
            float acc = bias;
            #pragma unroll 16
            for (int k = 0; k < 128; k++)
                acc = fmaf(hs[nn][k], W2s[k * 65 + j], acc);
            fs[nn][j] = acc;
        }
    }
    __syncthreads();

    for (int idx = t; idx < 8 * Ff; idx += 128) {
        int nn = idx / Ff, f = idx - nn * Ff;
        int n = n0 + nn;
        size_t tbase = (((size_t)b * Ll + (Ll - 1)) * Nn + n) * TEe;
        float val;
        if      (f < 64)  val = fs[nn][f];
        else if (f < 74)  val = tdf[tbase + f - 64];
        else if (f < 84)  val = dwf[tbase + f - 74];
        else if (f < 116) val = embd[(size_t)n * NDe + (f - 84)];
        else              val = embu[(size_t)n * NDe + (f - 116)];
        g_feat[((size_t)b * Nn + n) * Ff + f] = val;
    }
}

// ---------------------------------------------------------------------------
// Kernel 2: Q/K projections -> fp16 hi/lo (Q pre-scaled by 1/sqrt(H))
// ---------------------------------------------------------------------------
#define QK_SMEM ((Ff * 128 + 2 * F2 * 64) * (int)sizeof(float))

__global__ void __launch_bounds__(256) qk_kernel(
    const float* __restrict__ WQ, const float* __restrict__ WK)
{
    extern __shared__ float sm[];
    float* Fs  = sm;
    float* WQt = Fs + Ff * 128;
    float* WKt = WQt + F2 * 64;

    int node0 = blockIdx.x * 128;
    int b = blockIdx.y;
    int t = threadIdx.x;

    for (int i = t; i < 128 * Ff; i += 256) {
        int node = i / Ff, f = i - node * Ff;
        Fs[f * 128 + node] = g_feat[((size_t)b * Nn + node0 + node) * Ff + f];
    }
    for (int i = t; i < 64 * F2; i += 256) {
        int j = i / F2, f = i - j * F2;
        WQt[f * 64 + j] = WQ[i];
        WKt[f * 64 + j] = WK[i];
    }
    __syncthreads();

    int v = t >> 7, sel = (t >> 6) & 1, j = t & 63;
    const float* Wt = sel ? WKt : WQt;
    __half* dh = (sel ? g_Kh : g_Qh) + (size_t)(v * 2 + b) * Nn * Hh;
    __half* dl = (sel ? g_Kl : g_Ql) + (size_t)(v * 2 + b) * Nn * Hh;
    float scale = sel ? 1.0f : 0.125f;
    int ebase = 84 + 32 * v;

    for (int nb = 0; nb < 128; nb += 8) {
        float acc[8] = {0, 0, 0, 0, 0, 0, 0, 0};
        for (int f = 0; f < 84; f++) {
            float w = Wt[f * 64 + j];
            #pragma unroll
            for (int u = 0; u < 8; u++)
                acc[u] = fmaf(Fs[f * 128 + nb + u], w, acc[u]);
        }
        #pragma unroll 8
        for (int e = 0; e < 32; e++) {
            float w = Wt[(84 + e) * 64 + j];
            #pragma unroll
            for (int u = 0; u < 8; u++)
                acc[u] = fmaf(Fs[(ebase + e) * 128 + nb + u], w, acc[u]);
        }
        #pragma unroll
        for (int u = 0; u < 8; u++) {
            float sv = acc[u] * scale;
            __half h = __float2half_rn(sv);
            float lo = sv - __half2float(h);
            size_t idx = (size_t)(node0 + nb + u) * Hh + j;
            dh[idx] = h;
            dl[idx] = __float2half_rn(lo);
        }
    }
}

// ---------------------------------------------------------------------------
// Kernel 3: scores = (0.125*Q) @ K^T via fp16 HMMA, 3-pass hi/lo (exact).
// ---------------------------------------------------------------------------
#define SCSTRIDE 72
#define SC_ARR (128 * SCSTRIDE * 2)
#define SC_SMEM (4 * SC_ARR)

__global__ void __launch_bounds__(256, 2) scores_mma_kernel(int c)
{
    extern __shared__ char dsm[];
    int row0 = blockIdx.y * 128, col0 = blockIdx.x * 128;
    int t = threadIdx.x, wid = t >> 5, lane = t & 31;
    int g = lane >> 2, tig = lane & 3;
    int wm = wid >> 2, wn = wid & 3;
    int lq = lane >> 3, lr = lane & 7;

    size_t qb = (size_t)c * Nn * Hh;
    uint32_t sb = s2u(dsm);
    uint32_t aQh = sb, aQl = sb + SC_ARR, aKh = sb + 2 * SC_ARR,
             aKl = sb + 3 * SC_ARR;

    #pragma unroll
    for (int j = 0; j < 16; j++) {
        int idx = j * 256 + t;
        int arr = idx >> 10;
        int rem = idx & 1023;
        int rr = rem >> 3, seg = rem & 7;
        const __half* base = (arr == 0) ? g_Qh : (arr == 1) ? g_Ql
                           : (arr == 2) ? g_Kh : g_Kl;
        int grow = ((arr < 2) ? row0 : col0) + rr;
        cpa16(sb + (uint32_t)arr * SC_ARR + rr * (SCSTRIDE * 2) + seg * 16,
              base + qb + (size_t)grow * Hh + seg * 8);
    }
    cpa_commit();
    cpa_wait<0>();
    __syncthreads();

    float acc[4][4][4] = {};
    #pragma unroll
    for (int ks = 0; ks < 4; ks++) {
        int kk = ks * 16;
        uint32_t qh[4][4], ql[4][4], kh[4][2], kl[4][2];
        #pragma unroll
        for (int ma = 0; ma < 4; ma++) {
            int row = wm * 64 + ma * 16 + (lq & 1) * 8 + lr;
            int col = kk + (lq >> 1) * 8;
            uint32_t off = (uint32_t)(row * SCSTRIDE + col) * 2;
            ldm4(qh[ma], aQh + off);
            ldm4(ql[ma], aQl + off);
        }
        #pragma unroll
        for (int np = 0; np < 2; np++) {
            int nrow = wn * 32 + np * 16 + (lq >> 1) * 8 + lr;
            int col = kk + (lq & 1) * 8;
            uint32_t off = (uint32_t)(nrow * SCSTRIDE + col) * 2;
            uint32_t r4[4];
            ldm4(r4, aKh + off);
            kh[np * 2][0] = r4[0]; kh[np * 2][1] = r4[1];
            kh[np * 2 + 1][0] = r4[2]; kh[np * 2 + 1][1] = r4[3];
            ldm4(r4, aKl + off);
            kl[np * 2][0] = r4[0]; kl[np * 2][1] = r4[1];
            kl[np * 2 + 1][0] = r4[2]; kl[np * 2 + 1][1] = r4[3];
        }
        #pragma unroll
        for (int ma = 0; ma < 4; ma++)
            #pragma unroll
            for (int na = 0; na < 4; na++) {
                mma16816h(acc[ma][na], qh[ma], kh[na]);
                mma16816h(acc[ma][na], qh[ma], kl[na]);
                mma16816h(acc[ma][na], ql[ma], kh[na]);
            }
    }

    float* S = g_S + (size_t)c * Nn * Nn;
    #pragma unroll
    for (int ma = 0; ma < 4; ma++)
        #pragma unroll
        for (int rr = 0; rr < 2; rr++) {
            int n = row0 + wm * 64 + ma * 16 + g + rr * 8;
            #pragma unroll
            for (int na = 0; na < 4; na++) {
                int col = col0 + wn * 32 + na * 8 + tig * 2;
                *(float2*)(S + (size_t)n * Nn + col) =
                    make_float2(acc[ma][na][rr * 2 + 0], acc[ma][na][rr * 2 + 1]);
            }
        }
}

// ---------------------------------------------------------------------------
// Kernel 4: fused masked softmax + normalize; emits order-1 output + fp16 A
// ---------------------------------------------------------------------------
__global__ void __launch_bounds__(256) softmax_kernel(
    const float* __restrict__ mask0, const float* __restrict__ mask1,
    float* __restrict__ out, int c)
{
    int n = blockIdx.x, v = c >> 1, b = c & 1;
    int t = threadIdx.x;
    const float* srow = g_S + ((size_t)c * Nn + n) * Nn;
    const float* mrow = (v ? mask1 : mask0) + (size_t)n * Nn;

    float s[8];
    float lmax = -3.4e38f;
    #pragma unroll
    for (int i = 0; i < 8; i++) {
        s[i] = srow[t + i * 256];
        lmax = fmaxf(lmax, s[i]);
    }

    __shared__ float red[8];
    #pragma unroll
    for (int o = 16; o; o >>= 1)
        lmax = fmaxf(lmax, __shfl_xor_sync(0xffffffffu, lmax, o));
    if ((t & 31) == 0) red[t >> 5] = lmax;
    __syncthreads();
    float rmax = red[0];
    #pragma unroll
    for (int w = 1; w < 8; w++) rmax = fmaxf(rmax, red[w]);
    __syncthreads();

    float wv[8], lsum = 0.0f;
    #pragma unroll
    for (int i = 0; i < 8; i++) {
        wv[i] = (mrow[t + i * 256] + 1e-7f) * expf(s[i] - rmax);
        lsum += wv[i];
    }
    #pragma unroll
    for (int o = 16; o; o >>= 1)
        lsum += __shfl_xor_sync(0xffffffffu, lsum, o);
    if ((t & 31) == 0) red[t >> 5] = lsum;
    __syncthreads();
    float tot = 0.0f;
    #pragma unroll
    for (int w = 0; w < 8; w++) tot += red[w];
    float inv = 1.0f / tot;

    size_t abase = ((size_t)c * Nn + n) * Nn;
    float* orow = out + (size_t)(v * 2) * OUT_G + (size_t)(b * Nn + n) * KTt * Nn;
    #pragma unroll
    for (int i = 0; i < 8; i++) {
        int m = t + i * 256;
        float val = wv[i] * inv;
        g_Ah[abase + m] = __float2half_rn(val);
        float ov = (m == n) ? 0.0f : val;
        orow[m] = ov;
        orow[Nn + m] = ov;
        orow[2 * Nn + m] = ov;
    }
}

// ---------------------------------------------------------------------------
// Kernel 5: C = A @ A via fp16 mma.sync, single pass, B via ldmatrix.trans.
// CTA 128x128, 4 warps of 64x64, K-chunk 64, double-buffered cp.async.
// ---------------------------------------------------------------------------
#define ASTRIDE 72
#define BSTRIDE 136
#define A_B (128 * ASTRIDE * 2)
#define B_B (64 * BSTRIDE * 2)
#define BUF_B (A_B + B_B)
#define SQ_SMEM (2 * BUF_B)

__global__ void __launch_bounds__(128, 2) sq_mma_kernel(float* __restrict__ out,
                                                        int c)
{
    extern __shared__ char dsm[];
    int v = c >> 1, b = c & 1;
    int row0 = blockIdx.y * 128, col0 = blockIdx.x * 128;
    int t = threadIdx.x, wid = t >> 5, lane = t & 31;
    int g = lane >> 2, tig = lane & 3;
    int wm = wid >> 1, wn = wid & 1;
    int lq = lane >> 3, lr = lane & 7;

    size_t cb = (size_t)c * Nn * Nn;
    const __half* Ahg = g_Ah + cb;

    uint32_t sbase = s2u(dsm);
    float acc[4][8][4] = {};

    auto load_stage = [&](int s, int kc) {
        uint32_t sb = sbase + (uint32_t)s * BUF_B;
        int k0 = kc * 64;
        #pragma unroll
        for (int j = 0; j < 8; j++) {
            int idx = j * 128 + t;
            int rr = idx >> 3, seg = idx & 7;
            cpa16(sb + rr * (ASTRIDE * 2) + seg * 16,
                  Ahg + (size_t)(row0 + rr) * Nn + k0 + seg * 8);
        }
        #pragma unroll
        for (int j = 0; j < 8; j++) {
            int idx = j * 128 + t;
            int rr = idx >> 4, seg = idx & 15;
            cpa16(sb + A_B + rr * (BSTRIDE * 2) + seg * 16,
                  Ahg + (size_t)(k0 + rr) * Nn + col0 + seg * 8);
        }
        cpa_commit();
    };

    load_stage(0, 0);

    int buf = 0;
    for (int kc = 0; kc < 32; kc++) {
        if (kc + 1 < 32) {
            load_stage(buf ^ 1, kc + 1);
            cpa_wait<1>();
        } else {
            cpa_wait<0>();
        }
        __syncthreads();

        uint32_t sb = sbase + (uint32_t)buf * BUF_B;
        uint32_t aA = sb, aB = sb + A_B;

        #pragma unroll
        for (int ks = 0; ks < 4; ks++) {
            int kk = ks * 16;
            uint32_t ah[4][4], bh[8][2];
            #pragma unroll
            for (int ma = 0; ma < 4; ma++) {
                int row = wm * 64 + ma * 16 + (lq & 1) * 8 + lr;
                int col = kk + (lq >> 1) * 8;
                ldm4(ah[ma], aA + (uint32_t)(row * ASTRIDE + col) * 2);
            }
            #pragma unroll
            for (int np = 0; np < 4; np++) {
                int row_k = kk + (lq & 1) * 8 + lr;
                int col_n = wn * 64 + np * 16 + (lq >> 1) * 8;
                uint32_t r4[4];
                ldm4t(r4, aB + (uint32_t)(row_k * BSTRIDE + col_n) * 2);
                bh[np * 2][0] = r4[0]; bh[np * 2][1] = r4[1];
                bh[np * 2 + 1][0] = r4[2]; bh[np * 2 + 1][1] = r4[3];
            }
            #pragma unroll
            for (int ma = 0; ma < 4; ma++)
                #pragma unroll
                for (int na = 0; na < 8; na++)
                    mma16816h(acc[ma][na], ah[ma], bh[na]);
        }
        __syncthreads();
        buf ^= 1;
    }

    float* obase = out + (size_t)(v * 2 + 1) * OUT_G;
    #pragma unroll
    for (int ma = 0; ma < 4; ma++) {
        #pragma unroll
        for (int rr = 0; rr < 2; rr++) {
            int n = row0 + wm * 64 + ma * 16 + g + rr * 8;
            size_t orow = (size_t)(b * Nn + n) * (KTt * Nn);
            #pragma unroll
            for (int na = 0; na < 8; na++) {
                int col = col0 + wn * 64 + na * 8 + tig * 2;
                float v0 = acc[ma][na][rr * 2 + 0];
                float v1 = acc[ma][na][rr * 2 + 1];
                if (n == col)     v0 = 0.0f;
                if (n == col + 1) v1 = 0.0f;
                float2 o = make_float2(v0, v1);
                *(float2*)(obase + orow + col)          = o;
                *(float2*)(obase + orow + Nn + col)     = o;
                *(float2*)(obase + orow + 2 * Nn + col) = o;
            }
        }
    }
}

// ---------------------------------------------------------------------------
extern "C" void kernel_launch(void* const* d_in, const int* in_sizes, int n_in,
                              void* d_out, int out_size)
{
    const float* hist = (const float*)d_in[0];
    const float* embd = (const float*)d_in[1];
    const float* embu = (const float*)d_in[2];
    const float* tdf  = (const float*)d_in[3];
    const float* dwf  = (const float*)d_in[4];
    const float* m0   = (const float*)d_in[5];
    const float* m1   = (const float*)d_in[6];
    const float* W1   = (const float*)d_in[7];
    const float* b1   = (const float*)d_in[8];
    const float* gam  = (const float*)d_in[9];
    const float* bet  = (const float*)d_in[10];
    const float* mu   = (const float*)d_in[11];
    const float* var  = (const float*)d_in[12];
    const float* W2   = (const float*)d_in[13];
    const float* b2   = (const float*)d_in[14];
    const float* WQ   = (const float*)d_in[15];
    const float* WK   = (const float*)d_in[16];
    float* out = (float*)d_out;

    // One-time host-side resources (created on the un-captured correctness
    // run). 3 side streams ONLY — the 4-branch fork shape tripped the
    // graph-upload mem guard in rounds 8/10; the 3+origin shape passed in 7/9.
    static cudaStream_t st[3] = {nullptr, nullptr, nullptr};
    static cudaEvent_t evf = nullptr, evj[3] = {nullptr, nullptr, nullptr};
    if (st[0] == nullptr) {
        int loPri = 0, hiPri = 0;
        cudaDeviceGetStreamPriorityRange(&loPri, &hiPri);  // hiPri = highest
        for (int i = 0; i < 3; i++) {
            int pri = hiPri + i;
            if (pri > loPri) pri = loPri;
            cudaStreamCreateWithPriority(&st[i], cudaStreamNonBlocking, pri);
            cudaEventCreateWithFlags(&evj[i], cudaEventDisableTiming);
        }
        cudaEventCreateWithFlags(&evf, cudaEventDisableTiming);
        cudaFuncSetAttribute(qk_kernel,
                             cudaFuncAttributeMaxDynamicSharedMemorySize, QK_SMEM);
        cudaFuncSetAttribute(scores_mma_kernel,
                             cudaFuncAttributeMaxDynamicSharedMemorySize, SC_SMEM);
        cudaFuncSetAttribute(sq_mma_kernel,
                             cudaFuncAttributeMaxDynamicSharedMemorySize, SQ_SMEM);
    }

    feat_kernel<<<dim3(Nn / 8, Bb), 128>>>(hist, embd, embu, tdf, dwf,
                                           W1, b1, gam, bet, mu, var, W2, b2);
    qk_kernel<<<dim3(Nn / 128, Bb), 256, QK_SMEM>>>(WQ, WK);

    // Fork: combo 0 on the capture-origin stream, combos 1..3 on st[0..2]
    // with descending priorities (soft stagger, no extra graph edges).
    cudaEventRecord(evf, 0);
    for (int i = 0; i < 3; i++) cudaStreamWaitEvent(st[i], evf, 0);

    scores_mma_kernel<<<dim3(16, 16, 1), 256, SC_SMEM>>>(0);
    for (int i = 0; i < 3; i++)
        scores_mma_kernel<<<dim3(16, 16, 1), 256, SC_SMEM, st[i]>>>(i + 1);

    softmax_kernel<<<dim3(Nn, 1), 256>>>(m0, m1, out, 0);
    for (int i = 0; i < 3; i++)
        softmax_kernel<<<dim3(Nn, 1), 256, 0, st[i]>>>(m0, m1, out, i + 1);

    sq_mma_kernel<<<dim3(16, 16, 1), 128, SQ_SMEM>>>(out, 0);
    for (int i = 0; i < 3; i++)
        sq_mma_kernel<<<dim3(16, 16, 1), 128, SQ_SMEM, st[i]>>>(out, i + 1);

    // Join
    for (int i = 0; i < 3; i++) {
        cudaEventRecord(evj[i], st[i]);
        cudaStreamWaitEvent(0, evj[i], 0);
    }
}